// round 14
// baseline (speedup 1.0000x reference)
#include <cuda_runtime.h>
#include <cuda_bf16.h>
#include <float.h>
#include <cstdint>

// Problem constants
#define BB 8
#define CC 64
#define NN 4096
#define KK 32
#define HH 4
#define DD 16
#define ROWS (BB*NN)          // 32768
#define FULLMASK 0xffffffffu

// -------------------- device scratch --------------------
__device__ float    g_feat[ROWS*CC];   // (B,N,C) fp32
__device__ float    g_sqn[ROWS];       // squared norms
__device__ unsigned g_scores[(size_t)ROWS*NN];  // PACKED order-fixed scores (536 MB)
__device__ int      g_knn[ROWS*KK];    // top-K indices (in-batch n)
__device__ float    g_f0[ROWS*CC];     // feat + attention out
__device__ float    g_hid[(size_t)ROWS*256];    // MLP hidden (33.5 MB)
__device__ float    g_f2[ROWS*CC];     // f1 + ff (pre-BN2)
__device__ float    g_psum[512*CC];    // per-block BN partial sums
__device__ float    g_psq[512*CC];
__device__ float    g_mu[CC];
__device__ float    g_rs[CC];

// -------------------- warp helpers --------------------
__device__ __forceinline__ float warp_max32(float v){
#pragma unroll
  for (int o=16;o>0;o>>=1) v = fmaxf(v, __shfl_xor_sync(FULLMASK, v, o));
  return v;
}
__device__ __forceinline__ float warp_sum32(float v){
#pragma unroll
  for (int o=16;o>0;o>>=1) v += __shfl_xor_sync(FULLMASK, v, o);
  return v;
}
// packed f32x2 FMA (Blackwell native; ptxas won't auto-fuse)
__device__ __forceinline__ void ffma2(unsigned long long& d, unsigned long long a,
                                      unsigned long long b){
  asm("fma.rn.f32x2 %0, %1, %2, %0;" : "+l"(d) : "l"(a), "l"(b));
}
__device__ __forceinline__ float2 unpk(unsigned long long v){
  float2 r; asm("mov.b64 {%0, %1}, %2;" : "=f"(r.x), "=f"(r.y) : "l"(v));
  return r;
}
// order-preserving float->uint transform
__device__ __forceinline__ unsigned ofix(float v){
  unsigned u = __float_as_uint(v);
  return (u & 0x80000000u) ? ~u : (u | 0x80000000u);
}
// cp.async 16B
__device__ __forceinline__ void cp16(uint32_t dst, const void* src){
  asm volatile("cp.async.cg.shared.global [%0], [%1], 16;" :: "r"(dst), "l"(src));
}
#define CP_COMMIT() asm volatile("cp.async.commit_group;" ::: "memory")
#define CP_WAIT1()  asm volatile("cp.async.wait_group 1;" ::: "memory")
#define CP_WAIT0()  asm volatile("cp.async.wait_group 0;" ::: "memory")
__device__ __forceinline__ uint32_t smem_u32(const void* p){
  uint32_t a;
  asm("{ .reg .u64 t; cvta.to.shared.u64 t, %1; cvt.u32.u64 %0, t; }" : "=r"(a) : "l"(p));
  return a;
}

// -------------------- 1. transpose x (B,C,N) -> feat (B,N,C) --------------------
__global__ void transpose_kernel(const float* __restrict__ x){
  __shared__ float tile[32][33];
  int b  = blockIdx.z;
  int c0 = blockIdx.y * 32;
  int n0 = blockIdx.x * 32;
  int tx = threadIdx.x, ty = threadIdx.y;   // (32,8)
  const float* xb = x + (size_t)b*CC*NN;
#pragma unroll
  for (int i = 0; i < 32; i += 8)
    tile[ty+i][tx] = xb[(size_t)(c0+ty+i)*NN + n0 + tx];
  __syncthreads();
  float* fb = g_feat + (size_t)b*NN*CC;
#pragma unroll
  for (int i = 0; i < 32; i += 8)
    fb[(size_t)(n0+ty+i)*CC + c0 + tx] = tile[tx][ty+i];
}

// -------------------- 2. squared norms --------------------
__global__ void sqnorm_kernel(){
  int row = blockIdx.x*blockDim.x + threadIdx.x;
  if (row >= ROWS) return;
  const float4* f = (const float4*)(g_feat + (size_t)row*CC);
  float s = 0.f;
#pragma unroll
  for (int i=0;i<16;i++){ float4 v=f[i]; s += v.x*v.x+v.y*v.y+v.z*v.z+v.w*v.w; }
  g_sqn[row] = s;
}

// -------------------- 3a. symmetric Gram -> PACKED scores -----------------------
#define KNN_SMEM_BYTES ((8192*2 + 128)*4)

__global__ __launch_bounds__(256,3) void gram_kernel(const float* __restrict__ x){
  extern __shared__ float sm[];
  float2* fnT2 = (float2*)sm;          // [c][r] duplicated {v,v}
  float*  fmT  = sm + 8192;            // [c][m]  (c0-31 = half A, c32-63 = half B)
  float*  ssq  = sm + 16384;           // 128

  int b = blockIdx.y;
  int rb = blockIdx.x;                 // row-tile index 0..63
  int nbase = rb * 64;
  int tstart = rb >> 1;                // first m-tile (128-wide)
  const float* fb  = g_feat + (size_t)b*NN*CC;
  const float* xb  = x + (size_t)b*CC*NN;
  const float* sqb = g_sqn + (size_t)b*NN;
  int tid = threadIdx.x;
  int lane = tid & 31, wid = tid >> 5;
  int r0 = wid * 8;

  uint32_t fm_base = smem_u32(fmT);
  uint32_t sq_base = smem_u32(ssq);

  int lc   = tid >> 3;
  int lseg = tid & 7;
  const float* srcA = xb + (size_t)lc*NN      + lseg*16;
  const float* srcB = xb + (size_t)(lc+32)*NN + lseg*16;
  uint32_t     dstA = (uint32_t)((lc*128      + lseg*16)*4);
  uint32_t     dstB = (uint32_t)(((lc+32)*128 + lseg*16)*4);

  {
    const float* pA = srcA + tstart*128;
    const float* pB = srcB + tstart*128;
#pragma unroll
    for (int k = 0; k < 4; k++) cp16(fm_base + dstA + k*16, pA + k*4);
    CP_COMMIT();
#pragma unroll
    for (int k = 0; k < 4; k++) cp16(fm_base + dstB + k*16, pB + k*4);
    if (tid < 32) cp16(sq_base + tid*16, sqb + tstart*128 + tid*4);
    CP_COMMIT();
  }

  {
    int r = tid & 63, cg = tid >> 6;     // cg 0..3
#pragma unroll
    for (int it = 0; it < 4; it++){
      int c = (cg + it*4) * 4;
      float4 v = *(const float4*)(fb + (size_t)(nbase + r)*CC + c);
      fnT2[(c  )*64 + r] = make_float2(v.x, v.x);
      fnT2[(c+1)*64 + r] = make_float2(v.y, v.y);
      fnT2[(c+2)*64 + r] = make_float2(v.z, v.z);
      fnT2[(c+3)*64 + r] = make_float2(v.w, v.w);
    }
  }
  float rq[8];
#pragma unroll
  for (int i = 0; i < 8; i++) rq[i] = sqb[nbase + r0 + i];

  CP_WAIT1();
  __syncthreads();

  unsigned* scb = g_scores + (size_t)b*NN*NN;

  for (int mt = tstart; mt < 32; mt++){
    int mbase = mt * 128;

    unsigned long long acc[8][2];
#pragma unroll
    for (int i=0;i<8;i++){ acc[i][0]=0ull; acc[i][1]=0ull; }

#pragma unroll 4
    for (int c = 0; c < 32; c++){
      const ulonglong2* fp = (const ulonglong2*)(fnT2 + c*64 + r0);
      ulonglong2 fA = fp[0], fB = fp[1], fC = fp[2], fD = fp[3];
      ulonglong2 mm = *(const ulonglong2*)(fmT + c*128 + (lane<<2));
      ffma2(acc[0][0], fA.x, mm.x); ffma2(acc[0][1], fA.x, mm.y);
      ffma2(acc[1][0], fA.y, mm.x); ffma2(acc[1][1], fA.y, mm.y);
      ffma2(acc[2][0], fB.x, mm.x); ffma2(acc[2][1], fB.x, mm.y);
      ffma2(acc[3][0], fB.y, mm.x); ffma2(acc[3][1], fB.y, mm.y);
      ffma2(acc[4][0], fC.x, mm.x); ffma2(acc[4][1], fC.x, mm.y);
      ffma2(acc[5][0], fC.y, mm.x); ffma2(acc[5][1], fC.y, mm.y);
      ffma2(acc[6][0], fD.x, mm.x); ffma2(acc[6][1], fD.x, mm.y);
      ffma2(acc[7][0], fD.y, mm.x); ffma2(acc[7][1], fD.y, mm.y);
    }
    __syncthreads();

    if (mt < 31){
      const float* s = srcA + mbase + 128;
#pragma unroll
      for (int k = 0; k < 4; k++) cp16(fm_base + dstA + k*16, s + k*4);
      CP_COMMIT();
      CP_WAIT1();
    } else {
      CP_WAIT0();
    }
    __syncthreads();

#pragma unroll 4
    for (int c = 32; c < 64; c++){
      const ulonglong2* fp = (const ulonglong2*)(fnT2 + c*64 + r0);
      ulonglong2 fA = fp[0], fB = fp[1], fC = fp[2], fD = fp[3];
      ulonglong2 mm = *(const ulonglong2*)(fmT + c*128 + (lane<<2));
      ffma2(acc[0][0], fA.x, mm.x); ffma2(acc[0][1], fA.x, mm.y);
      ffma2(acc[1][0], fA.y, mm.x); ffma2(acc[1][1], fA.y, mm.y);
      ffma2(acc[2][0], fB.x, mm.x); ffma2(acc[2][1], fB.x, mm.y);
      ffma2(acc[3][0], fB.y, mm.x); ffma2(acc[3][1], fB.y, mm.y);
      ffma2(acc[4][0], fC.x, mm.x); ffma2(acc[4][1], fC.x, mm.y);
      ffma2(acc[5][0], fC.y, mm.x); ffma2(acc[5][1], fC.y, mm.y);
      ffma2(acc[6][0], fD.x, mm.x); ffma2(acc[6][1], fD.x, mm.y);
      ffma2(acc[7][0], fD.y, mm.x); ffma2(acc[7][1], fD.y, mm.y);
    }

    {
      float4 sq4 = *(const float4*)(ssq + (lane<<2));
      unsigned mv0[8], mv1[8], mv2[8], mv3[8];
#pragma unroll
      for (int i = 0; i < 8; i++){
        float2 dA = unpk(acc[i][0]);
        float2 dB = unpk(acc[i][1]);
        unsigned u0 = ofix(fmaf(2.f, dA.x, -sq4.x));
        unsigned u1 = ofix(fmaf(2.f, dA.y, -sq4.y));
        unsigned u2 = ofix(fmaf(2.f, dB.x, -sq4.z));
        unsigned u3 = ofix(fmaf(2.f, dB.y, -sq4.w));
        *(uint4*)(scb + (size_t)(nbase + r0 + i)*NN + mbase + (lane<<2))
            = make_uint4(u0, u1, u2, u3);
        mv0[i] = ofix(fmaf(2.f, dA.x, -rq[i]));
        mv1[i] = ofix(fmaf(2.f, dA.y, -rq[i]));
        mv2[i] = ofix(fmaf(2.f, dB.x, -rq[i]));
        mv3[i] = ofix(fmaf(2.f, dB.y, -rq[i]));
      }
      int mrow = mbase + (lane<<2);
      unsigned* mp0 = scb + (size_t)(mrow  )*NN + nbase + r0;
      unsigned* mp1 = scb + (size_t)(mrow+1)*NN + nbase + r0;
      unsigned* mp2 = scb + (size_t)(mrow+2)*NN + nbase + r0;
      unsigned* mp3 = scb + (size_t)(mrow+3)*NN + nbase + r0;
      *(uint4*)(mp0)   = make_uint4(mv0[0], mv0[1], mv0[2], mv0[3]);
      *(uint4*)(mp0+4) = make_uint4(mv0[4], mv0[5], mv0[6], mv0[7]);
      *(uint4*)(mp1)   = make_uint4(mv1[0], mv1[1], mv1[2], mv1[3]);
      *(uint4*)(mp1+4) = make_uint4(mv1[4], mv1[5], mv1[6], mv1[7]);
      *(uint4*)(mp2)   = make_uint4(mv2[0], mv2[1], mv2[2], mv2[3]);
      *(uint4*)(mp2+4) = make_uint4(mv2[4], mv2[5], mv2[6], mv2[7]);
      *(uint4*)(mp3)   = make_uint4(mv3[0], mv3[1], mv3[2], mv3[3]);
      *(uint4*)(mp3+4) = make_uint4(mv3[4], mv3[5], mv3[6], mv3[7]);
    }
    __syncthreads();

    if (mt < 31){
      const float* s = srcB + mbase + 128;
#pragma unroll
      for (int k = 0; k < 4; k++) cp16(fm_base + dstB + k*16, s + k*4);
      if (tid < 32) cp16(sq_base + tid*16, sqb + mbase + 128 + tid*4);
      CP_COMMIT();
      CP_WAIT1();
      __syncthreads();
    }
  }
}

// -------------------- 3b. topk: one warp per row, packed-score stream -----------
__global__ __launch_bounds__(256) void topk_kernel(){
  int tid = threadIdx.x;
  int lane = tid & 31, wid = tid >> 5;
  int row = blockIdx.x * 8 + wid;
  const uint4* srow = (const uint4*)(g_scores + (size_t)row*NN);

  unsigned cur_lo = (unsigned)lane; int cur_idx = 0; unsigned thr = 0u;

  for (int mt = 0; mt < 32; mt++){
    uint4 u = srow[mt*32 + lane];
    unsigned u0 = u.x, u1 = u.y, u2 = u.z, u3 = u.w;

    if (mt == 0){
      unsigned m01 = max(u0, u1), m23 = max(u2, u3);
      unsigned um4 = max(m01, m23);
      int jm = (um4 == u0) ? 0 : (um4 == u1) ? 1 : (um4 == u2) ? 2 : 3;
      cur_lo  = (um4 & ~31u) | (unsigned)lane;
      cur_idx = (lane<<2) + jm;
      thr = __reduce_min_sync(FULLMASK, cur_lo);
      if (jm == 0) u0 = 0u; else if (jm == 1) u1 = 0u;
      else if (jm == 2) u2 = 0u; else u3 = 0u;
    }

    unsigned um = max(max(u0,u1), max(u2,u3));
    if (!__any_sync(FULLMASK, um > thr)) continue;
    unsigned uu[4] = {u0,u1,u2,u3};
#pragma unroll
    for (int j=0;j<4;j++){
      unsigned cu = uu[j];
      int      ci = mt*128 + (lane<<2) + j;
      unsigned mask = __ballot_sync(FULLMASK, cu > thr);
      while (mask){
        int src = __ffs(mask) - 1; mask &= mask - 1;
        unsigned c_u = __shfl_sync(FULLMASK, cu, src);
        int      c_i = __shfl_sync(FULLMASK, ci, src);
        unsigned mp = __reduce_min_sync(FULLMASK, cur_lo);
        if (c_u > mp){
          if (lane == (int)(mp & 31u)){ cur_lo = (c_u & ~31u) | (unsigned)lane; cur_idx = c_i; }
          thr = mp;
        }
      }
    }
  }
  g_knn[(size_t)row*KK + lane] = cur_idx;
}

// -------------------- 4. attention: raw-gather prefetch + subtract-late ----------
#define AT_WARPS 16
#define AT_WBUF 2688
#define DIFF_LD 68

__global__ __launch_bounds__(512) void attn_kernel(const float* __restrict__ wq,
                                                   const float* __restrict__ wk,
                                                   const float* __restrict__ wv){
  extern __shared__ float smf[];
  float2* wq2 = (float2*)smf;
  float2* wv2 = wq2 + 2048;
  float2* wk2 = wv2 + 2048;
  int tid = threadIdx.x;
  int lane = tid & 31, wid = tid >> 5;
  float* wb    = smf + 12288 + wid*AT_WBUF;
  float* sraw  = wb;
  float* sfn   = wb + 2176;
  float* sq    = wb + 2240;
  float* sqk   = wb + 2304;
  float* sattn = wb + 2560;
  float* swd   = sqk;

  int rowbase = blockIdx.x * (AT_WARPS*4);
  uint32_t raw_dst = smem_u32(sraw + lane*DIFF_LD);

  {
    int row = rowbase + wid*4;
    int b = row >> 12;
    int nbr = g_knn[(size_t)row*KK + lane];
    const float* src = g_feat + ((size_t)(b<<12) + nbr)*CC;
#pragma unroll
    for (int k = 0; k < 16; k++) cp16(raw_dst + k*16, src + k*4);
    CP_COMMIT();
  }

  for (int idx = tid; idx < 2048; idx += 512){
    int cc = idx >> 5, oo = idx & 31;
    wq2[idx] = make_float2(wq[oo*64 + cc], wq[(oo+32)*64 + cc]);
    wv2[idx] = make_float2(wv[oo*64 + cc], wv[(oo+32)*64 + cc]);
    int o = idx >> 5, c = idx & 31;
    wk2[idx] = make_float2(wk[o*64 + c], wk[o*64 + c + 32]);
  }
  __syncthreads();

  float s0 = 0.f, q0s = 0.f, s1 = 0.f, q1s = 0.f;

  for (int rr = 0; rr < 4; rr++){
    int row = rowbase + wid*4 + rr;

    sfn[lane]      = g_feat[(size_t)row*CC + lane];
    sfn[lane + 32] = g_feat[(size_t)row*CC + lane + 32];
    __syncwarp();

    {
      float q0 = 0.f, q1 = 0.f;
#pragma unroll
      for (int c4 = 0; c4 < 16; c4++){
        float4 f = *(const float4*)(sfn + c4*4);
        float2 w0 = wq2[(c4*4  )*32 + lane];
        float2 w1 = wq2[(c4*4+1)*32 + lane];
        float2 w2 = wq2[(c4*4+2)*32 + lane];
        float2 w3 = wq2[(c4*4+3)*32 + lane];
        q0 += f.x*w0.x + f.y*w1.x + f.z*w2.x + f.w*w3.x;
        q1 += f.x*w0.y + f.y*w1.y + f.z*w2.y + f.w*w3.y;
      }
      sq[lane] = q0; sq[lane+32] = q1;
    }
    __syncwarp();

    float qkfn[4];
    {
      float a[8];
#pragma unroll
      for (int t=0;t<8;t++) a[t]=0.f;
#pragma unroll
      for (int o = 0; o < 64; o++){
        int h = o >> 4;
        float qb = sq[o];
        float2 w = wk2[o*32 + lane];
        a[h*2  ] += qb*w.x;
        a[h*2+1] += qb*w.y;
      }
      float f0v = sfn[lane], f1v = sfn[lane+32];
#pragma unroll
      for (int h=0;h<4;h++){
        sqk[h*64 + lane]      = a[h*2];
        sqk[h*64 + lane + 32] = a[h*2+1];
        qkfn[h] = warp_sum32(a[h*2]*f0v + a[h*2+1]*f1v);
      }
    }
    CP_WAIT0();
    __syncwarp();

    {
      float e0=0.f,e1=0.f,e2=0.f,e3=0.f;
      const float4* rrow = (const float4*)(sraw + lane*DIFF_LD);
#pragma unroll
      for (int c4 = 0; c4 < 16; c4++){
        float4 d = rrow[c4];
        float4 k0 = *(const float4*)(sqk + 0*64 + c4*4);
        float4 k1 = *(const float4*)(sqk + 1*64 + c4*4);
        float4 k2 = *(const float4*)(sqk + 2*64 + c4*4);
        float4 k3 = *(const float4*)(sqk + 3*64 + c4*4);
        e0 += d.x*k0.x + d.y*k0.y + d.z*k0.z + d.w*k0.w;
        e1 += d.x*k1.x + d.y*k1.y + d.z*k1.z + d.w*k1.w;
        e2 += d.x*k2.x + d.y*k2.y + d.z*k2.z + d.w*k2.w;
        e3 += d.x*k3.x + d.y*k3.y + d.z*k3.z + d.w*k3.w;
      }
      float e[4] = {(e0-qkfn[0])*0.25f, (e1-qkfn[1])*0.25f,
                    (e2-qkfn[2])*0.25f, (e3-qkfn[3])*0.25f};
      float a[4];
#pragma unroll
      for (int h=0;h<4;h++){
        float mx = warp_max32(e[h]);
        float ex = __expf(e[h]-mx);
        float s  = warp_sum32(ex);
        a[h] = ex / s;
      }
      *(float4*)(sattn + lane*4) = make_float4(a[0],a[1],a[2],a[3]);
    }
    __syncwarp();

    {
      float w[8];
#pragma unroll
      for (int t=0;t<8;t++) w[t]=0.f;
#pragma unroll
      for (int k = 0; k < 32; k++){
        float4 at = *(const float4*)(sattn + k*4);
        float d0 = sraw[k*DIFF_LD + lane];
        float d1 = sraw[k*DIFF_LD + lane + 32];
        w[0]+=at.x*d0; w[1]+=at.x*d1;
        w[2]+=at.y*d0; w[3]+=at.y*d1;
        w[4]+=at.z*d0; w[5]+=at.z*d1;
        w[6]+=at.w*d0; w[7]+=at.w*d1;
      }
      float f0v = sfn[lane], f1v = sfn[lane+32];
#pragma unroll
      for (int h=0;h<4;h++){ w[h*2] -= f0v; w[h*2+1] -= f1v; }
      __syncwarp();
#pragma unroll
      for (int h=0;h<4;h++){
        swd[h*64 + lane]      = w[h*2];
        swd[h*64 + lane + 32] = w[h*2+1];
      }
    }
    __syncwarp();

    if (rr < 3){
      int nrow = row + 1;
      int nb = nrow >> 12;
      int nbr = g_knn[(size_t)nrow*KK + lane];
      const float* src = g_feat + ((size_t)(nb<<12) + nbr)*CC;
#pragma unroll
      for (int k = 0; k < 16; k++) cp16(raw_dst + k*16, src + k*4);
      CP_COMMIT();
    }

    {
      int h0 = lane >> 4;
      float o0 = 0.f, o1 = 0.f;
#pragma unroll
      for (int c4 = 0; c4 < 16; c4++){
        float4 d0 = *(const float4*)(swd + h0*64     + c4*4);
        float4 d1 = *(const float4*)(swd + (h0+2)*64 + c4*4);
        float2 w0 = wv2[(c4*4  )*32 + lane];
        float2 w1 = wv2[(c4*4+1)*32 + lane];
        float2 w2 = wv2[(c4*4+2)*32 + lane];
        float2 w3 = wv2[(c4*4+3)*32 + lane];
        o0 += d0.x*w0.x + d0.y*w1.x + d0.z*w2.x + d0.w*w3.x;
        o1 += d1.x*w0.y + d1.y*w1.y + d1.z*w2.y + d1.w*w3.y;
      }
      float f00 = sfn[lane]      + o0;
      float f01 = sfn[lane + 32] + o1;
      g_f0[(size_t)row*CC + lane]      = f00;
      g_f0[(size_t)row*CC + lane + 32] = f01;
      s0 += f00; q0s += f00*f00;
      s1 += f01; q1s += f01*f01;
    }
    __syncwarp();
  }

  __syncthreads();
  float2* sc0 = (float2*)smf;
  float2* sc1 = sc0 + 512;
  sc0[wid*32 + lane] = make_float2(s0, q0s);
  sc1[wid*32 + lane] = make_float2(s1, q1s);
  __syncthreads();
  if (tid < 64){
    const float2* srcp = (tid < 32) ? (sc0 + tid) : (sc1 + (tid - 32));
    float s = 0.f, q = 0.f;
#pragma unroll
    for (int w = 0; w < 16; w++){ float2 v = srcp[w*32]; s += v.x; q += v.y; }
    g_psum[blockIdx.x*64 + tid] = s;
    g_psq [blockIdx.x*64 + tid] = q;
  }
}

// -------------------- 5. BN finalize (512 partials) --------------------
__global__ void bn_finalize_kernel(){
  __shared__ float ps[256], pq[256];
  int c = threadIdx.x & 63, part = threadIdx.x >> 6;
  float s = 0.f, q = 0.f;
  for (int i = part; i < 512; i += 4){ s += g_psum[i*64 + c]; q += g_psq[i*64 + c]; }
  ps[threadIdx.x] = s; pq[threadIdx.x] = q;
  __syncthreads();
  if (threadIdx.x < 64){
    s = ps[c] + ps[c+64] + ps[c+128] + ps[c+192];
    q = pq[c] + pq[c+64] + pq[c+128] + pq[c+192];
    float m   = s * (1.f/32768.f);
    float var = q * (1.f/32768.f) - m*m;
    g_mu[c] = m;
    g_rs[c] = rsqrtf(var + 1e-5f);
  }
}

// -------------------- 6a. MLP layer 1: BN1-normalize + w1 + LeakyReLU ----------
#define MLP1_SMEM ((16384 + 256)*4)
__global__ __launch_bounds__(256,3) void mlp1_kernel(const float* __restrict__ w1,
                                                     const float* __restrict__ g1,
                                                     const float* __restrict__ b1){
  extern __shared__ float smf[];
  float* w1T  = smf;              // [c][o] 64x256
  float* sf1T = smf + 16384;      // [c][j] 64x4
  __shared__ float ssc[64], ssh[64];
  int tid = threadIdx.x;

  {
    int o = tid;
#pragma unroll
    for (int c4 = 0; c4 < 16; c4++){
      float4 v = *(const float4*)(w1 + o*64 + c4*4);
      int c = c4*4;
      w1T[c*256+o]=v.x; w1T[(c+1)*256+o]=v.y; w1T[(c+2)*256+o]=v.z; w1T[(c+3)*256+o]=v.w;
    }
  }
  if (tid < 64){
    float r = g_rs[tid] * g1[tid];
    ssc[tid] = r;
    ssh[tid] = b1[tid] - g_mu[tid]*r;
  }
  __syncthreads();

  int rowbase = blockIdx.x * 64;
  for (int it = 0; it < 16; it++){
    int row0 = rowbase + it*4;
    {
      int c = tid >> 2, j = tid & 3;
      sf1T[tid] = g_f0[(size_t)(row0+j)*CC + c]*ssc[c] + ssh[c];
    }
    __syncthreads();
    float h0=0.f,h1=0.f,h2=0.f,h3=0.f;
#pragma unroll
    for (int c = 0; c < 64; c++){
      float w = w1T[c*256 + tid];
      float4 f = *(const float4*)(sf1T + c*4);
      h0+=f.x*w; h1+=f.y*w; h2+=f.z*w; h3+=f.w*w;
    }
    h0 = (h0>0.f)?h0:0.2f*h0; h1 = (h1>0.f)?h1:0.2f*h1;
    h2 = (h2>0.f)?h2:0.2f*h2; h3 = (h3>0.f)?h3:0.2f*h3;
    g_hid[(size_t)(row0+0)*256 + tid] = h0;
    g_hid[(size_t)(row0+1)*256 + tid] = h1;
    g_hid[(size_t)(row0+2)*256 + tid] = h2;
    g_hid[(size_t)(row0+3)*256 + tid] = h3;
    __syncthreads();
  }
}

// -------------------- 6b. MLP layer 2: w2 + residual + fused BN2 stats ----------
#define MLP2_SMEM ((16384 + 1024 + 256 + 1024)*4)
__global__ __launch_bounds__(256,3) void mlp2_kernel(const float* __restrict__ w2,
                                                     const float* __restrict__ g1,
                                                     const float* __restrict__ b1){
  extern __shared__ float smf[];
  float* w2T   = smf;              // [o][c] 256x64
  float* shT   = smf + 16384;      // [o][j] 256x4
  float* sf1T  = smf + 17408;      // [c][j] 64x4
  float* spart = smf + 17664;      // 1024
  __shared__ float ssc[64], ssh[64];
  int tid = threadIdx.x;

  {
    int c = tid & 63, o4b = tid >> 6;
#pragma unroll
    for (int it = 0; it < 16; it++){
      int o2 = (o4b + 4*it) * 4;
      float4 v = *(const float4*)(w2 + c*256 + o2);
      w2T[o2*64+c]=v.x; w2T[(o2+1)*64+c]=v.y; w2T[(o2+2)*64+c]=v.z; w2T[(o2+3)*64+c]=v.w;
    }
  }
  if (tid < 64){
    float r = g_rs[tid] * g1[tid];
    ssc[tid] = r;
    ssh[tid] = b1[tid] - g_mu[tid]*r;
  }
  __syncthreads();

  int rowbase = blockIdx.x * 64;
  float s_loc = 0.f, q_loc = 0.f;
  for (int it = 0; it < 16; it++){
    int row0 = rowbase + it*4;
    {
      int c = tid >> 2, j = tid & 3;
      sf1T[tid] = g_f0[(size_t)(row0+j)*CC + c]*ssc[c] + ssh[c];
    }
#pragma unroll
    for (int j = 0; j < 4; j++)
      shT[tid*4 + j] = g_hid[(size_t)(row0+j)*256 + tid];
    __syncthreads();
    {
      int c = tid & 63, part = tid >> 6;
      float p0=0.f,p1=0.f,p2=0.f,p3=0.f;
#pragma unroll
      for (int oo = 0; oo < 64; oo++){
        int o = part*64 + oo;
        float w = w2T[o*64 + c];
        float4 hv = *(const float4*)(shT + o*4);
        p0+=hv.x*w; p1+=hv.y*w; p2+=hv.z*w; p3+=hv.w*w;
      }
      spart[(0*4+part)*64 + c] = p0;
      spart[(1*4+part)*64 + c] = p1;
      spart[(2*4+part)*64 + c] = p2;
      spart[(3*4+part)*64 + c] = p3;
    }
    __syncthreads();
    {
      int c = tid & 63, j = tid >> 6;
      float ff = spart[(j*4+0)*64+c] + spart[(j*4+1)*64+c]
               + spart[(j*4+2)*64+c] + spart[(j*4+3)*64+c];
      float v = sf1T[c*4+j] + ff;
      g_f2[(size_t)(row0+j)*CC + c] = v;
      s_loc += v; q_loc += v*v;
    }
    __syncthreads();
  }

  {
    int c = tid & 63, j = tid >> 6;
    spart[j*64 + c]       = s_loc;
    spart[(4+j)*64 + c]   = q_loc;
  }
  __syncthreads();
  if (tid < 64){
    float s = spart[tid] + spart[64+tid] + spart[128+tid] + spart[192+tid];
    float q = spart[256+tid] + spart[320+tid] + spart[384+tid] + spart[448+tid];
    g_psum[blockIdx.x*64 + tid] = s;
    g_psq [blockIdx.x*64 + tid] = q;
  }
}

// -------------------- 7. BN2-normalize + transpose to (B,C,N) --------------------
__global__ void out_kernel(const float* __restrict__ g2, const float* __restrict__ b2,
                           float* __restrict__ out){
  __shared__ float tile[32][33];
  int b  = blockIdx.z;
  int c0 = blockIdx.y * 32;
  int n0 = blockIdx.x * 32;
  int tx = threadIdx.x, ty = threadIdx.y;
  const float* fb = g_f2 + (size_t)b*NN*CC;
#pragma unroll
  for (int i = 0; i < 32; i += 8)
    tile[ty+i][tx] = fb[(size_t)(n0+ty+i)*CC + c0 + tx];
  __syncthreads();
#pragma unroll
  for (int i = 0; i < 32; i += 8){
    int c = c0 + ty + i;
    float sc = g_rs[c]*g2[c];
    float sh = b2[c] - g_mu[c]*sc;
    out[((size_t)b*CC + c)*NN + n0 + tx] = tile[tx][ty+i]*sc + sh;
  }
}

// -------------------- launch --------------------
extern "C" void kernel_launch(void* const* d_in, const int* in_sizes, int n_in,
                              void* d_out, int out_size){
  (void)in_sizes; (void)n_in; (void)out_size;
  const float* x  = (const float*)d_in[0];
  const float* wq = (const float*)d_in[1];
  const float* wk = (const float*)d_in[2];
  const float* wv = (const float*)d_in[3];
  const float* w1 = (const float*)d_in[4];
  const float* w2 = (const float*)d_in[5];
  const float* g1 = (const float*)d_in[6];
  const float* b1 = (const float*)d_in[7];
  const float* g2 = (const float*)d_in[8];
  const float* b2 = (const float*)d_in[9];
  float* out = (float*)d_out;

  const int ATTN_SMEM = (12288 + AT_WARPS*AT_WBUF) * 4;
  cudaFuncSetAttribute(gram_kernel, cudaFuncAttributeMaxDynamicSharedMemorySize, KNN_SMEM_BYTES);
  cudaFuncSetAttribute(attn_kernel, cudaFuncAttributeMaxDynamicSharedMemorySize, ATTN_SMEM);
  cudaFuncSetAttribute(mlp1_kernel, cudaFuncAttributeMaxDynamicSharedMemorySize, MLP1_SMEM);
  cudaFuncSetAttribute(mlp2_kernel, cudaFuncAttributeMaxDynamicSharedMemorySize, MLP2_SMEM);

  transpose_kernel<<<dim3(NN/32, CC/32, BB), dim3(32,8)>>>(x);
  sqnorm_kernel<<<ROWS/256, 256>>>();
  gram_kernel<<<dim3(NN/64, BB), 256, KNN_SMEM_BYTES>>>(x);
  topk_kernel<<<ROWS/8, 256>>>();
  attn_kernel<<<ROWS/(AT_WARPS*4), 512, ATTN_SMEM>>>(wq, wk, wv);
  bn_finalize_kernel<<<1, 256>>>();
  mlp1_kernel<<<ROWS/64, 256, MLP1_SMEM>>>(w1, g1, b1);
  mlp2_kernel<<<ROWS/64, 256, MLP2_SMEM>>>(w2, g1, b1);
  bn_finalize_kernel<<<1, 256>>>();
  out_kernel<<<dim3(NN/32, CC/32, BB), dim3(32,8)>>>(g2, b2, out);
}

// round 15
// speedup vs baseline: 1.5360x; 1.5360x over previous
#include <cuda_runtime.h>
#include <cuda_bf16.h>
#include <float.h>
#include <cstdint>

// Problem constants
#define BB 8
#define CC 64
#define NN 4096
#define KK 32
#define HH 4
#define DD 16
#define ROWS (BB*NN)          // 32768
#define FULLMASK 0xffffffffu

// -------------------- device scratch --------------------
__device__ float g_feat[ROWS*CC];   // (B,N,C) fp32
__device__ float g_sqn[ROWS];       // squared norms
__device__ float g_scores[(size_t)ROWS*NN];  // raw Gram dots (536 MB)
__device__ int   g_knn[ROWS*KK];    // top-K indices (in-batch n)
__device__ float g_f0[ROWS*CC];     // feat + attention out
__device__ float g_f2[ROWS*CC];     // f1 + ff (pre-BN2)
__device__ float g_psum[512*CC];    // per-block BN partial sums
__device__ float g_psq[512*CC];
__device__ float g_mu[CC];
__device__ float g_rs[CC];

// -------------------- warp helpers --------------------
__device__ __forceinline__ float warp_max32(float v){
#pragma unroll
  for (int o=16;o>0;o>>=1) v = fmaxf(v, __shfl_xor_sync(FULLMASK, v, o));
  return v;
}
__device__ __forceinline__ float warp_sum32(float v){
#pragma unroll
  for (int o=16;o>0;o>>=1) v += __shfl_xor_sync(FULLMASK, v, o);
  return v;
}
// packed f32x2 FMA (Blackwell native; ptxas won't auto-fuse)
__device__ __forceinline__ void ffma2(unsigned long long& d, unsigned long long a,
                                      unsigned long long b){
  asm("fma.rn.f32x2 %0, %1, %2, %0;" : "+l"(d) : "l"(a), "l"(b));
}
__device__ __forceinline__ float2 unpk(unsigned long long v){
  float2 r; asm("mov.b64 {%0, %1}, %2;" : "=f"(r.x), "=f"(r.y) : "l"(v));
  return r;
}
// order-preserving float->uint transform
__device__ __forceinline__ unsigned ofix(float v){
  unsigned u = __float_as_uint(v);
  return (u & 0x80000000u) ? ~u : (u | 0x80000000u);
}
// cp.async 16B
__device__ __forceinline__ void cp16(uint32_t dst, const void* src){
  asm volatile("cp.async.cg.shared.global [%0], [%1], 16;" :: "r"(dst), "l"(src));
}
#define CP_COMMIT() asm volatile("cp.async.commit_group;" ::: "memory")
#define CP_WAIT1()  asm volatile("cp.async.wait_group 1;" ::: "memory")
#define CP_WAIT0()  asm volatile("cp.async.wait_group 0;" ::: "memory")
__device__ __forceinline__ uint32_t smem_u32(const void* p){
  uint32_t a;
  asm("{ .reg .u64 t; cvta.to.shared.u64 t, %1; cvt.u32.u64 %0, t; }" : "=r"(a) : "l"(p));
  return a;
}

// -------------------- 1. transpose x (B,C,N) -> feat (B,N,C) --------------------
__global__ void transpose_kernel(const float* __restrict__ x){
  __shared__ float tile[32][33];
  int b  = blockIdx.z;
  int c0 = blockIdx.y * 32;
  int n0 = blockIdx.x * 32;
  int tx = threadIdx.x, ty = threadIdx.y;   // (32,8)
  const float* xb = x + (size_t)b*CC*NN;
#pragma unroll
  for (int i = 0; i < 32; i += 8)
    tile[ty+i][tx] = xb[(size_t)(c0+ty+i)*NN + n0 + tx];
  __syncthreads();
  float* fb = g_feat + (size_t)b*NN*CC;
#pragma unroll
  for (int i = 0; i < 32; i += 8)
    fb[(size_t)(n0+ty+i)*CC + c0 + tx] = tile[tx][ty+i];
}

// -------------------- 2. squared norms --------------------
__global__ void sqnorm_kernel(){
  int row = blockIdx.x*blockDim.x + threadIdx.x;
  if (row >= ROWS) return;
  const float4* f = (const float4*)(g_feat + (size_t)row*CC);
  float s = 0.f;
#pragma unroll
  for (int i=0;i<16;i++){ float4 v=f[i]; s += v.x*v.x+v.y*v.y+v.z*v.z+v.w*v.w; }
  g_sqn[row] = s;
}

// -------------------- 3a. symmetric Gram: upper triangle + mirrored writes ------
#define KNN_SMEM_BYTES ((8192*2)*4)

__global__ __launch_bounds__(256,3) void gram_kernel(const float* __restrict__ x){
  extern __shared__ float sm[];
  float2* fnT2 = (float2*)sm;          // [c][r] duplicated {v,v}
  float*  fmT  = sm + 8192;            // [c][m]  (c0-31 = half A, c32-63 = half B)

  int b = blockIdx.y;
  int rb = blockIdx.x;                 // row-tile index 0..63
  int nbase = rb * 64;
  int tstart = rb >> 1;                // first m-tile (128-wide)
  const float* fb = g_feat + (size_t)b*NN*CC;
  const float* xb = x + (size_t)b*CC*NN;
  int tid = threadIdx.x;
  int lane = tid & 31, wid = tid >> 5;
  int r0 = wid * 8;

  uint32_t fm_base = smem_u32(fmT);

  int lc   = tid >> 3;
  int lseg = tid & 7;
  const float* srcA = xb + (size_t)lc*NN      + lseg*16;
  const float* srcB = xb + (size_t)(lc+32)*NN + lseg*16;
  uint32_t     dstA = (uint32_t)((lc*128      + lseg*16)*4);
  uint32_t     dstB = (uint32_t)(((lc+32)*128 + lseg*16)*4);

  // prologue: issue first tile halves as two groups
  {
    const float* pA = srcA + tstart*128;
    const float* pB = srcB + tstart*128;
#pragma unroll
    for (int k = 0; k < 4; k++) cp16(fm_base + dstA + k*16, pA + k*4);
    CP_COMMIT();
#pragma unroll
    for (int k = 0; k < 4; k++) cp16(fm_base + dstB + k*16, pB + k*4);
    CP_COMMIT();
  }

  // load fnT2 (64 rows) transposed + duplicated (from row-major g_feat)
  {
    int r = tid & 63, cg = tid >> 6;     // cg 0..3
#pragma unroll
    for (int it = 0; it < 4; it++){
      int c = (cg + it*4) * 4;
      float4 v = *(const float4*)(fb + (size_t)(nbase + r)*CC + c);
      fnT2[(c  )*64 + r] = make_float2(v.x, v.x);
      fnT2[(c+1)*64 + r] = make_float2(v.y, v.y);
      fnT2[(c+2)*64 + r] = make_float2(v.z, v.z);
      fnT2[(c+3)*64 + r] = make_float2(v.w, v.w);
    }
  }

  CP_WAIT1();          // half A of first tile ready
  __syncthreads();

  float* scb = g_scores + (size_t)b*NN*NN;

  for (int mt = tstart; mt < 32; mt++){
    int mbase = mt * 128;

    unsigned long long acc[8][2];
#pragma unroll
    for (int i=0;i<8;i++){ acc[i][0]=0ull; acc[i][1]=0ull; }

    // ---- gram over c-half A (c 0..31) ----
#pragma unroll 4
    for (int c = 0; c < 32; c++){
      const ulonglong2* fp = (const ulonglong2*)(fnT2 + c*64 + r0);
      ulonglong2 fA = fp[0], fB = fp[1], fC = fp[2], fD = fp[3];
      ulonglong2 mm = *(const ulonglong2*)(fmT + c*128 + (lane<<2));
      ffma2(acc[0][0], fA.x, mm.x); ffma2(acc[0][1], fA.x, mm.y);
      ffma2(acc[1][0], fA.y, mm.x); ffma2(acc[1][1], fA.y, mm.y);
      ffma2(acc[2][0], fB.x, mm.x); ffma2(acc[2][1], fB.x, mm.y);
      ffma2(acc[3][0], fB.y, mm.x); ffma2(acc[3][1], fB.y, mm.y);
      ffma2(acc[4][0], fC.x, mm.x); ffma2(acc[4][1], fC.x, mm.y);
      ffma2(acc[5][0], fC.y, mm.x); ffma2(acc[5][1], fC.y, mm.y);
      ffma2(acc[6][0], fD.x, mm.x); ffma2(acc[6][1], fD.x, mm.y);
      ffma2(acc[7][0], fD.y, mm.x); ffma2(acc[7][1], fD.y, mm.y);
    }
    __syncthreads();                 // all readers of half A done

    if (mt < 31){                    // refill half A with tile mt+1
      const float* s = srcA + mbase + 128;
#pragma unroll
      for (int k = 0; k < 4; k++) cp16(fm_base + dstA + k*16, s + k*4);
      CP_COMMIT();
      CP_WAIT1();                    // half B of tile mt ready
    } else {
      CP_WAIT0();
    }
    __syncthreads();

    // ---- gram over c-half B (c 32..63) ----
#pragma unroll 4
    for (int c = 32; c < 64; c++){
      const ulonglong2* fp = (const ulonglong2*)(fnT2 + c*64 + r0);
      ulonglong2 fA = fp[0], fB = fp[1], fC = fp[2], fD = fp[3];
      ulonglong2 mm = *(const ulonglong2*)(fmT + c*128 + (lane<<2));
      ffma2(acc[0][0], fA.x, mm.x); ffma2(acc[0][1], fA.x, mm.y);
      ffma2(acc[1][0], fA.y, mm.x); ffma2(acc[1][1], fA.y, mm.y);
      ffma2(acc[2][0], fB.x, mm.x); ffma2(acc[2][1], fB.x, mm.y);
      ffma2(acc[3][0], fB.y, mm.x); ffma2(acc[3][1], fB.y, mm.y);
      ffma2(acc[4][0], fC.x, mm.x); ffma2(acc[4][1], fC.x, mm.y);
      ffma2(acc[5][0], fC.y, mm.x); ffma2(acc[5][1], fC.y, mm.y);
      ffma2(acc[6][0], fD.x, mm.x); ffma2(acc[6][1], fD.x, mm.y);
      ffma2(acc[7][0], fD.y, mm.x); ffma2(acc[7][1], fD.y, mm.y);
    }

    // ---- stream direct rows + mirrored transpose ----
    {
      float va0[8], va1[8], va2[8], va3[8];
#pragma unroll
      for (int i = 0; i < 8; i++){
        float2 dA = unpk(acc[i][0]);
        float2 dB = unpk(acc[i][1]);
        *(float4*)(scb + (size_t)(nbase + r0 + i)*NN + mbase + (lane<<2))
            = make_float4(dA.x, dA.y, dB.x, dB.y);
        va0[i] = dA.x; va1[i] = dA.y; va2[i] = dB.x; va3[i] = dB.y;
      }
      int mrow = mbase + (lane<<2);
      float* mp0 = scb + (size_t)(mrow  )*NN + nbase + r0;
      float* mp1 = scb + (size_t)(mrow+1)*NN + nbase + r0;
      float* mp2 = scb + (size_t)(mrow+2)*NN + nbase + r0;
      float* mp3 = scb + (size_t)(mrow+3)*NN + nbase + r0;
      *(float4*)(mp0)   = make_float4(va0[0], va0[1], va0[2], va0[3]);
      *(float4*)(mp0+4) = make_float4(va0[4], va0[5], va0[6], va0[7]);
      *(float4*)(mp1)   = make_float4(va1[0], va1[1], va1[2], va1[3]);
      *(float4*)(mp1+4) = make_float4(va1[4], va1[5], va1[6], va1[7]);
      *(float4*)(mp2)   = make_float4(va2[0], va2[1], va2[2], va2[3]);
      *(float4*)(mp2+4) = make_float4(va2[4], va2[5], va2[6], va2[7]);
      *(float4*)(mp3)   = make_float4(va3[0], va3[1], va3[2], va3[3]);
      *(float4*)(mp3+4) = make_float4(va3[4], va3[5], va3[6], va3[7]);
    }
    __syncthreads();                 // readers of half B done

    if (mt < 31){                    // refill half B with tile mt+1
      const float* s = srcB + mbase + 128;
#pragma unroll
      for (int k = 0; k < 4; k++) cp16(fm_base + dstB + k*16, s + k*4);
      CP_COMMIT();
      CP_WAIT1();                    // half A of tile mt+1 ready
      __syncthreads();
    }
  }
}

// -------------------- 3b. topk: one warp per row, streaming top-32 --------------
__global__ __launch_bounds__(256) void topk_kernel(){
  int tid = threadIdx.x;
  int lane = tid & 31, wid = tid >> 5;
  int row = blockIdx.x * 8 + wid;
  int b = row >> 12;
  const float4* srow = (const float4*)(g_scores + (size_t)row*NN);
  const float4* sqr  = (const float4*)(g_sqn + (size_t)b*NN);

  unsigned cur_lo = (unsigned)lane; int cur_idx = 0; unsigned thr = 0u;

  for (int mt = 0; mt < 32; mt++){
    float4 g  = srow[mt*32 + lane];
    float4 sq = sqr [mt*32 + lane];
    unsigned u0 = ofix(fmaf(2.f, g.x, -sq.x));
    unsigned u1 = ofix(fmaf(2.f, g.y, -sq.y));
    unsigned u2 = ofix(fmaf(2.f, g.z, -sq.z));
    unsigned u3 = ofix(fmaf(2.f, g.w, -sq.w));

    if (mt == 0){
      unsigned m01 = max(u0, u1), m23 = max(u2, u3);
      unsigned um4 = max(m01, m23);
      int jm = (um4 == u0) ? 0 : (um4 == u1) ? 1 : (um4 == u2) ? 2 : 3;
      cur_lo  = (um4 & ~31u) | (unsigned)lane;
      cur_idx = (lane<<2) + jm;
      thr = __reduce_min_sync(FULLMASK, cur_lo);
      if (jm == 0) u0 = 0u; else if (jm == 1) u1 = 0u;
      else if (jm == 2) u2 = 0u; else u3 = 0u;
    }

    unsigned um = max(max(u0,u1), max(u2,u3));
    if (!__any_sync(FULLMASK, um > thr)) continue;
    unsigned uu[4] = {u0,u1,u2,u3};
#pragma unroll
    for (int j=0;j<4;j++){
      unsigned cu = uu[j];
      int      ci = mt*128 + (lane<<2) + j;
      unsigned mask = __ballot_sync(FULLMASK, cu > thr);
      while (mask){
        int src = __ffs(mask) - 1; mask &= mask - 1;
        unsigned c_u = __shfl_sync(FULLMASK, cu, src);
        int      c_i = __shfl_sync(FULLMASK, ci, src);
        unsigned mp = __reduce_min_sync(FULLMASK, cur_lo);
        if (c_u > mp){
          if (lane == (int)(mp & 31u)){ cur_lo = (c_u & ~31u) | (unsigned)lane; cur_idx = c_i; }
          thr = mp;   // lazy lower bound (pre-insertion min)
        }
      }
    }
  }
  g_knn[(size_t)row*KK + lane] = cur_idx;
}

// -------------------- 4. factorized attention + fused BN1 stats ------------------
#define AT_WARPS 16
#define AT_WBUF 2688
#define DIFF_LD 68

__global__ __launch_bounds__(512) void attn_kernel(const float* __restrict__ wq,
                                                   const float* __restrict__ wk,
                                                   const float* __restrict__ wv){
  extern __shared__ float smf[];
  float2* wq2 = (float2*)smf;
  float2* wv2 = wq2 + 2048;
  float2* wk2 = wv2 + 2048;
  int tid = threadIdx.x;
  int lane = tid & 31, wid = tid >> 5;
  float* wb    = smf + 12288 + wid*AT_WBUF;
  float* sdiff = wb;
  float* sfn   = wb + 2176;
  float* sq    = wb + 2240;
  float* sqk   = wb + 2304;
  float* sattn = wb + 2560;
  float* swd   = sqk;

  for (int idx = tid; idx < 2048; idx += 512){
    int cc = idx >> 5, oo = idx & 31;
    wq2[idx] = make_float2(wq[oo*64 + cc], wq[(oo+32)*64 + cc]);
    wv2[idx] = make_float2(wv[oo*64 + cc], wv[(oo+32)*64 + cc]);
    int o = idx >> 5, c = idx & 31;
    wk2[idx] = make_float2(wk[o*64 + c], wk[o*64 + c + 32]);
  }
  __syncthreads();

  int rowbase = blockIdx.x * (AT_WARPS*4);
  float s0 = 0.f, q0s = 0.f, s1 = 0.f, q1s = 0.f;   // BN1 partials

  for (int rr = 0; rr < 4; rr++){
    int row = rowbase + wid*4 + rr;
    int b = row >> 12;

    sfn[lane]      = g_feat[(size_t)row*CC + lane];
    sfn[lane + 32] = g_feat[(size_t)row*CC + lane + 32];
    __syncwarp();

    {
      int nbr = g_knn[(size_t)row*KK + lane];
      const float4* frow = (const float4*)(g_feat + ((size_t)(b<<12) + nbr)*CC);
      float4* drow = (float4*)(sdiff + lane*DIFF_LD);
#pragma unroll
      for (int c4 = 0; c4 < 16; c4++){
        float4 v = frow[c4];
        float4 f = *(const float4*)(sfn + c4*4);
        drow[c4] = make_float4(v.x-f.x, v.y-f.y, v.z-f.z, v.w-f.w);
      }
    }

    {
      float q0 = 0.f, q1 = 0.f;
#pragma unroll
      for (int c4 = 0; c4 < 16; c4++){
        float4 f = *(const float4*)(sfn + c4*4);
        float2 w0 = wq2[(c4*4  )*32 + lane];
        float2 w1 = wq2[(c4*4+1)*32 + lane];
        float2 w2 = wq2[(c4*4+2)*32 + lane];
        float2 w3 = wq2[(c4*4+3)*32 + lane];
        q0 += f.x*w0.x + f.y*w1.x + f.z*w2.x + f.w*w3.x;
        q1 += f.x*w0.y + f.y*w1.y + f.z*w2.y + f.w*w3.y;
      }
      sq[lane] = q0; sq[lane+32] = q1;
    }
    __syncwarp();

    {
      float a[8];
#pragma unroll
      for (int t=0;t<8;t++) a[t]=0.f;
#pragma unroll
      for (int o = 0; o < 64; o++){
        int h = o >> 4;
        float qb = sq[o];
        float2 w = wk2[o*32 + lane];
        a[h*2  ] += qb*w.x;
        a[h*2+1] += qb*w.y;
      }
#pragma unroll
      for (int h=0;h<4;h++){
        sqk[h*64 + lane]      = a[h*2];
        sqk[h*64 + lane + 32] = a[h*2+1];
      }
    }
    __syncwarp();

    {
      float e0=0.f,e1=0.f,e2=0.f,e3=0.f;
      const float4* drow = (const float4*)(sdiff + lane*DIFF_LD);
#pragma unroll
      for (int c4 = 0; c4 < 16; c4++){
        float4 d = drow[c4];
        float4 k0 = *(const float4*)(sqk + 0*64 + c4*4);
        float4 k1 = *(const float4*)(sqk + 1*64 + c4*4);
        float4 k2 = *(const float4*)(sqk + 2*64 + c4*4);
        float4 k3 = *(const float4*)(sqk + 3*64 + c4*4);
        e0 += d.x*k0.x + d.y*k0.y + d.z*k0.z + d.w*k0.w;
        e1 += d.x*k1.x + d.y*k1.y + d.z*k1.z + d.w*k1.w;
        e2 += d.x*k2.x + d.y*k2.y + d.z*k2.z + d.w*k2.w;
        e3 += d.x*k3.x + d.y*k3.y + d.z*k3.z + d.w*k3.w;
      }
      float e[4] = {e0*0.25f, e1*0.25f, e2*0.25f, e3*0.25f};
      float a[4];
#pragma unroll
      for (int h=0;h<4;h++){
        float mx = warp_max32(e[h]);
        float ex = __expf(e[h]-mx);
        float s  = warp_sum32(ex);
        a[h] = ex / s;
      }
      *(float4*)(sattn + lane*4) = make_float4(a[0],a[1],a[2],a[3]);
    }
    __syncwarp();

    {
      float w[8];
#pragma unroll
      for (int t=0;t<8;t++) w[t]=0.f;
#pragma unroll
      for (int k = 0; k < 32; k++){
        float4 at = *(const float4*)(sattn + k*4);
        float d0 = sdiff[k*DIFF_LD + lane];
        float d1 = sdiff[k*DIFF_LD + lane + 32];
        w[0]+=at.x*d0; w[1]+=at.x*d1;
        w[2]+=at.y*d0; w[3]+=at.y*d1;
        w[4]+=at.z*d0; w[5]+=at.z*d1;
        w[6]+=at.w*d0; w[7]+=at.w*d1;
      }
      __syncwarp();
#pragma unroll
      for (int h=0;h<4;h++){
        swd[h*64 + lane]      = w[h*2];
        swd[h*64 + lane + 32] = w[h*2+1];
      }
    }
    __syncwarp();

    {
      int h0 = lane >> 4;
      float o0 = 0.f, o1 = 0.f;
#pragma unroll
      for (int c4 = 0; c4 < 16; c4++){
        float4 d0 = *(const float4*)(swd + h0*64     + c4*4);
        float4 d1 = *(const float4*)(swd + (h0+2)*64 + c4*4);
        float2 w0 = wv2[(c4*4  )*32 + lane];
        float2 w1 = wv2[(c4*4+1)*32 + lane];
        float2 w2 = wv2[(c4*4+2)*32 + lane];
        float2 w3 = wv2[(c4*4+3)*32 + lane];
        o0 += d0.x*w0.x + d0.y*w1.x + d0.z*w2.x + d0.w*w3.x;
        o1 += d1.x*w0.y + d1.y*w1.y + d1.z*w2.y + d1.w*w3.y;
      }
      float f00 = sfn[lane]      + o0;
      float f01 = sfn[lane + 32] + o1;
      g_f0[(size_t)row*CC + lane]      = f00;
      g_f0[(size_t)row*CC + lane + 32] = f01;
      s0 += f00; q0s += f00*f00;
      s1 += f01; q1s += f01*f01;
    }
    __syncwarp();
  }

  // fused BN1 stats: block-local reduce (reuses wq2/wv2 region after sync)
  __syncthreads();
  float2* sc0 = (float2*)smf;          // [warp][c0..31]
  float2* sc1 = sc0 + 512;             // [warp][c32..63]
  sc0[wid*32 + lane] = make_float2(s0, q0s);
  sc1[wid*32 + lane] = make_float2(s1, q1s);
  __syncthreads();
  if (tid < 64){
    const float2* srcp = (tid < 32) ? (sc0 + tid) : (sc1 + (tid - 32));
    float s = 0.f, q = 0.f;
#pragma unroll
    for (int w = 0; w < 16; w++){ float2 v = srcp[w*32]; s += v.x; q += v.y; }
    g_psum[blockIdx.x*64 + tid] = s;
    g_psq [blockIdx.x*64 + tid] = q;
  }
}

// -------------------- 5. BN finalize (512 partials) --------------------
__global__ void bn_finalize_kernel(){
  __shared__ float ps[256], pq[256];
  int c = threadIdx.x & 63, part = threadIdx.x >> 6;   // 256 threads
  float s = 0.f, q = 0.f;
  for (int i = part; i < 512; i += 4){ s += g_psum[i*64 + c]; q += g_psq[i*64 + c]; }
  ps[threadIdx.x] = s; pq[threadIdx.x] = q;
  __syncthreads();
  if (threadIdx.x < 64){
    s = ps[c] + ps[c+64] + ps[c+128] + ps[c+192];
    q = pq[c] + pq[c+64] + pq[c+128] + pq[c+192];
    float m   = s * (1.f/32768.f);
    float var = q * (1.f/32768.f) - m*m;
    g_mu[c] = m;
    g_rs[c] = rsqrtf(var + 1e-5f);
  }
}

// -------------------- 6. BN1-normalize + MLP + residual + fused BN2 stats --------
__global__ __launch_bounds__(256) void mlp_kernel(const float* __restrict__ w1,
                                                  const float* __restrict__ w2,
                                                  const float* __restrict__ g1,
                                                  const float* __restrict__ b1){
  extern __shared__ float smf[];
  float* w1T   = smf;
  float* w2T   = smf + 16384;
  float* sf1T  = smf + 32768;
  float* shT   = smf + 33024;
  float* spart = smf + 34048;
  __shared__ float ssc[64], ssh[64];
  int tid = threadIdx.x;

  {
    int o = tid;
#pragma unroll
    for (int c4 = 0; c4 < 16; c4++){
      float4 v = *(const float4*)(w1 + o*64 + c4*4);
      int c = c4*4;
      w1T[c*256+o]=v.x; w1T[(c+1)*256+o]=v.y; w1T[(c+2)*256+o]=v.z; w1T[(c+3)*256+o]=v.w;
    }
    int c = tid & 63, o4b = tid >> 6;
#pragma unroll
    for (int it = 0; it < 16; it++){
      int o2 = (o4b + 4*it) * 4;
      float4 v = *(const float4*)(w2 + c*256 + o2);
      w2T[o2*64+c]=v.x; w2T[(o2+1)*64+c]=v.y; w2T[(o2+2)*64+c]=v.z; w2T[(o2+3)*64+c]=v.w;
    }
  }
  if (tid < 64){
    float r = g_rs[tid] * g1[tid];
    ssc[tid] = r;
    ssh[tid] = b1[tid] - g_mu[tid]*r;
  }
  __syncthreads();

  int rowbase = blockIdx.x * 64;
  float s_loc = 0.f, q_loc = 0.f;
  for (int it = 0; it < 16; it++){
    int row0 = rowbase + it*4;
    {
      int c = tid >> 2, j = tid & 3;
      sf1T[tid] = g_f0[(size_t)(row0+j)*CC + c]*ssc[c] + ssh[c];
    }
    __syncthreads();
    float h0=0.f,h1=0.f,h2=0.f,h3=0.f;
#pragma unroll
    for (int c = 0; c < 64; c++){
      float w = w1T[c*256 + tid];
      float4 f = *(const float4*)(sf1T + c*4);
      h0+=f.x*w; h1+=f.y*w; h2+=f.z*w; h3+=f.w*w;
    }
    h0 = (h0>0.f)?h0:0.2f*h0; h1 = (h1>0.f)?h1:0.2f*h1;
    h2 = (h2>0.f)?h2:0.2f*h2; h3 = (h3>0.f)?h3:0.2f*h3;
    *(float4*)(shT + tid*4) = make_float4(h0,h1,h2,h3);
    __syncthreads();
    {
      int c = tid & 63, part = tid >> 6;
      float p0=0.f,p1=0.f,p2=0.f,p3=0.f;
#pragma unroll
      for (int oo = 0; oo < 64; oo++){
        int o = part*64 + oo;
        float w = w2T[o*64 + c];
        float4 hv = *(const float4*)(shT + o*4);
        p0+=hv.x*w; p1+=hv.y*w; p2+=hv.z*w; p3+=hv.w*w;
      }
      spart[(0*4+part)*64 + c] = p0;
      spart[(1*4+part)*64 + c] = p1;
      spart[(2*4+part)*64 + c] = p2;
      spart[(3*4+part)*64 + c] = p3;
    }
    __syncthreads();
    {
      int c = tid & 63, j = tid >> 6;
      float ff = spart[(j*4+0)*64+c] + spart[(j*4+1)*64+c]
               + spart[(j*4+2)*64+c] + spart[(j*4+3)*64+c];
      float v = sf1T[c*4+j] + ff;
      g_f2[(size_t)(row0+j)*CC + c] = v;
      s_loc += v; q_loc += v*v;
    }
    __syncthreads();
  }

  {
    int c = tid & 63, j = tid >> 6;
    spart[j*64 + c]       = s_loc;
    spart[(4+j)*64 + c]   = q_loc;
  }
  __syncthreads();
  if (tid < 64){
    float s = spart[tid] + spart[64+tid] + spart[128+tid] + spart[192+tid];
    float q = spart[256+tid] + spart[320+tid] + spart[384+tid] + spart[448+tid];
    g_psum[blockIdx.x*64 + tid] = s;
    g_psq [blockIdx.x*64 + tid] = q;
  }
}

// -------------------- 7. BN2-normalize + transpose to (B,C,N) --------------------
__global__ void out_kernel(const float* __restrict__ g2, const float* __restrict__ b2,
                           float* __restrict__ out){
  __shared__ float tile[32][33];
  int b  = blockIdx.z;
  int c0 = blockIdx.y * 32;
  int n0 = blockIdx.x * 32;
  int tx = threadIdx.x, ty = threadIdx.y;
  const float* fb = g_f2 + (size_t)b*NN*CC;
#pragma unroll
  for (int i = 0; i < 32; i += 8)
    tile[ty+i][tx] = fb[(size_t)(n0+ty+i)*CC + c0 + tx];
  __syncthreads();
#pragma unroll
  for (int i = 0; i < 32; i += 8){
    int c = c0 + ty + i;
    float sc = g_rs[c]*g2[c];
    float sh = b2[c] - g_mu[c]*sc;
    out[((size_t)b*CC + c)*NN + n0 + tx] = tile[tx][ty+i]*sc + sh;
  }
}

// -------------------- launch --------------------
extern "C" void kernel_launch(void* const* d_in, const int* in_sizes, int n_in,
                              void* d_out, int out_size){
  (void)in_sizes; (void)n_in; (void)out_size;
  const float* x  = (const float*)d_in[0];
  const float* wq = (const float*)d_in[1];
  const float* wk = (const float*)d_in[2];
  const float* wv = (const float*)d_in[3];
  const float* w1 = (const float*)d_in[4];
  const float* w2 = (const float*)d_in[5];
  const float* g1 = (const float*)d_in[6];
  const float* b1 = (const float*)d_in[7];
  const float* g2 = (const float*)d_in[8];
  const float* b2 = (const float*)d_in[9];
  float* out = (float*)d_out;

  const int ATTN_SMEM = (12288 + AT_WARPS*AT_WBUF) * 4;
  const int MLP_SMEM  = (16384 + 16384 + 256 + 1024 + 1024) * 4;
  cudaFuncSetAttribute(gram_kernel, cudaFuncAttributeMaxDynamicSharedMemorySize, KNN_SMEM_BYTES);
  cudaFuncSetAttribute(attn_kernel, cudaFuncAttributeMaxDynamicSharedMemorySize, ATTN_SMEM);
  cudaFuncSetAttribute(mlp_kernel,  cudaFuncAttributeMaxDynamicSharedMemorySize, MLP_SMEM);

  transpose_kernel<<<dim3(NN/32, CC/32, BB), dim3(32,8)>>>(x);
  sqnorm_kernel<<<ROWS/256, 256>>>();
  gram_kernel<<<dim3(NN/64, BB), 256, KNN_SMEM_BYTES>>>(x);
  topk_kernel<<<ROWS/8, 256>>>();
  attn_kernel<<<ROWS/(AT_WARPS*4), 512, ATTN_SMEM>>>(wq, wk, wv);
  bn_finalize_kernel<<<1, 256>>>();
  mlp_kernel<<<ROWS/64, 256, MLP_SMEM>>>(w1, w2, g1, b1);
  bn_finalize_kernel<<<1, 256>>>();
  out_kernel<<<dim3(NN/32, CC/32, BB), dim3(32,8)>>>(g2, b2, out);
}

// round 16
// speedup vs baseline: 1.5369x; 1.0006x over previous
#include <cuda_runtime.h>
#include <cuda_bf16.h>
#include <float.h>
#include <cstdint>

// Problem constants
#define BB 8
#define CC 64
#define NN 4096
#define KK 32
#define HH 4
#define DD 16
#define ROWS (BB*NN)          // 32768
#define FULLMASK 0xffffffffu

// -------------------- device scratch --------------------
__device__ float g_feat[ROWS*CC];   // (B,N,C) fp32
__device__ float g_sqn[ROWS];       // squared norms
__device__ float g_scores[(size_t)ROWS*NN];  // raw Gram dots (536 MB)
__device__ int   g_knn[ROWS*KK];    // top-K indices (in-batch n)
__device__ float g_f0[ROWS*CC];     // feat + attention out
__device__ float g_hid[(size_t)ROWS*256];    // MLP hidden (33.5 MB)
__device__ float g_f2[ROWS*CC];     // f1 + ff (pre-BN2)
__device__ float g_psum[512*CC];    // per-block BN partial sums
__device__ float g_psq[512*CC];
__device__ float g_mu[CC];
__device__ float g_rs[CC];

// -------------------- warp helpers --------------------
__device__ __forceinline__ float warp_max32(float v){
#pragma unroll
  for (int o=16;o>0;o>>=1) v = fmaxf(v, __shfl_xor_sync(FULLMASK, v, o));
  return v;
}
__device__ __forceinline__ float warp_sum32(float v){
#pragma unroll
  for (int o=16;o>0;o>>=1) v += __shfl_xor_sync(FULLMASK, v, o);
  return v;
}
// packed f32x2 FMA (Blackwell native; ptxas won't auto-fuse)
__device__ __forceinline__ void ffma2(unsigned long long& d, unsigned long long a,
                                      unsigned long long b){
  asm("fma.rn.f32x2 %0, %1, %2, %0;" : "+l"(d) : "l"(a), "l"(b));
}
__device__ __forceinline__ float2 unpk(unsigned long long v){
  float2 r; asm("mov.b64 {%0, %1}, %2;" : "=f"(r.x), "=f"(r.y) : "l"(v));
  return r;
}
// order-preserving float->uint transform
__device__ __forceinline__ unsigned ofix(float v){
  unsigned u = __float_as_uint(v);
  return (u & 0x80000000u) ? ~u : (u | 0x80000000u);
}
// cp.async 16B
__device__ __forceinline__ void cp16(uint32_t dst, const void* src){
  asm volatile("cp.async.cg.shared.global [%0], [%1], 16;" :: "r"(dst), "l"(src));
}
#define CP_COMMIT() asm volatile("cp.async.commit_group;" ::: "memory")
#define CP_WAIT1()  asm volatile("cp.async.wait_group 1;" ::: "memory")
#define CP_WAIT0()  asm volatile("cp.async.wait_group 0;" ::: "memory")
__device__ __forceinline__ uint32_t smem_u32(const void* p){
  uint32_t a;
  asm("{ .reg .u64 t; cvta.to.shared.u64 t, %1; cvt.u32.u64 %0, t; }" : "=r"(a) : "l"(p));
  return a;
}

// -------------------- 1. transpose x (B,C,N) -> feat (B,N,C) --------------------
__global__ void transpose_kernel(const float* __restrict__ x){
  __shared__ float tile[32][33];
  int b  = blockIdx.z;
  int c0 = blockIdx.y * 32;
  int n0 = blockIdx.x * 32;
  int tx = threadIdx.x, ty = threadIdx.y;   // (32,8)
  const float* xb = x + (size_t)b*CC*NN;
#pragma unroll
  for (int i = 0; i < 32; i += 8)
    tile[ty+i][tx] = xb[(size_t)(c0+ty+i)*NN + n0 + tx];
  __syncthreads();
  float* fb = g_feat + (size_t)b*NN*CC;
#pragma unroll
  for (int i = 0; i < 32; i += 8)
    fb[(size_t)(n0+ty+i)*CC + c0 + tx] = tile[tx][ty+i];
}

// -------------------- 2. squared norms --------------------
__global__ void sqnorm_kernel(){
  int row = blockIdx.x*blockDim.x + threadIdx.x;
  if (row >= ROWS) return;
  const float4* f = (const float4*)(g_feat + (size_t)row*CC);
  float s = 0.f;
#pragma unroll
  for (int i=0;i<16;i++){ float4 v=f[i]; s += v.x*v.x+v.y*v.y+v.z*v.z+v.w*v.w; }
  g_sqn[row] = s;
}

// -------------------- 3a. symmetric Gram: upper triangle + mirrored writes ------
#define KNN_SMEM_BYTES ((8192*2)*4)

__global__ __launch_bounds__(256,3) void gram_kernel(const float* __restrict__ x){
  extern __shared__ float sm[];
  float2* fnT2 = (float2*)sm;          // [c][r] duplicated {v,v}
  float*  fmT  = sm + 8192;            // [c][m]  (c0-31 = half A, c32-63 = half B)

  int b = blockIdx.y;
  int rb = blockIdx.x;                 // row-tile index 0..63
  int nbase = rb * 64;
  int tstart = rb >> 1;                // first m-tile (128-wide)
  const float* fb = g_feat + (size_t)b*NN*CC;
  const float* xb = x + (size_t)b*CC*NN;
  int tid = threadIdx.x;
  int lane = tid & 31, wid = tid >> 5;
  int r0 = wid * 8;

  uint32_t fm_base = smem_u32(fmT);

  int lc   = tid >> 3;
  int lseg = tid & 7;
  const float* srcA = xb + (size_t)lc*NN      + lseg*16;
  const float* srcB = xb + (size_t)(lc+32)*NN + lseg*16;
  uint32_t     dstA = (uint32_t)((lc*128      + lseg*16)*4);
  uint32_t     dstB = (uint32_t)(((lc+32)*128 + lseg*16)*4);

  // prologue: issue first tile halves as two groups
  {
    const float* pA = srcA + tstart*128;
    const float* pB = srcB + tstart*128;
#pragma unroll
    for (int k = 0; k < 4; k++) cp16(fm_base + dstA + k*16, pA + k*4);
    CP_COMMIT();
#pragma unroll
    for (int k = 0; k < 4; k++) cp16(fm_base + dstB + k*16, pB + k*4);
    CP_COMMIT();
  }

  // load fnT2 (64 rows) transposed + duplicated (from row-major g_feat)
  {
    int r = tid & 63, cg = tid >> 6;     // cg 0..3
#pragma unroll
    for (int it = 0; it < 4; it++){
      int c = (cg + it*4) * 4;
      float4 v = *(const float4*)(fb + (size_t)(nbase + r)*CC + c);
      fnT2[(c  )*64 + r] = make_float2(v.x, v.x);
      fnT2[(c+1)*64 + r] = make_float2(v.y, v.y);
      fnT2[(c+2)*64 + r] = make_float2(v.z, v.z);
      fnT2[(c+3)*64 + r] = make_float2(v.w, v.w);
    }
  }

  CP_WAIT1();          // half A of first tile ready
  __syncthreads();

  float* scb = g_scores + (size_t)b*NN*NN;

  for (int mt = tstart; mt < 32; mt++){
    int mbase = mt * 128;

    unsigned long long acc[8][2];
#pragma unroll
    for (int i=0;i<8;i++){ acc[i][0]=0ull; acc[i][1]=0ull; }

    // ---- gram over c-half A (c 0..31) ----
#pragma unroll 4
    for (int c = 0; c < 32; c++){
      const ulonglong2* fp = (const ulonglong2*)(fnT2 + c*64 + r0);
      ulonglong2 fA = fp[0], fB = fp[1], fC = fp[2], fD = fp[3];
      ulonglong2 mm = *(const ulonglong2*)(fmT + c*128 + (lane<<2));
      ffma2(acc[0][0], fA.x, mm.x); ffma2(acc[0][1], fA.x, mm.y);
      ffma2(acc[1][0], fA.y, mm.x); ffma2(acc[1][1], fA.y, mm.y);
      ffma2(acc[2][0], fB.x, mm.x); ffma2(acc[2][1], fB.x, mm.y);
      ffma2(acc[3][0], fB.y, mm.x); ffma2(acc[3][1], fB.y, mm.y);
      ffma2(acc[4][0], fC.x, mm.x); ffma2(acc[4][1], fC.x, mm.y);
      ffma2(acc[5][0], fC.y, mm.x); ffma2(acc[5][1], fC.y, mm.y);
      ffma2(acc[6][0], fD.x, mm.x); ffma2(acc[6][1], fD.x, mm.y);
      ffma2(acc[7][0], fD.y, mm.x); ffma2(acc[7][1], fD.y, mm.y);
    }
    __syncthreads();                 // all readers of half A done

    if (mt < 31){                    // refill half A with tile mt+1
      const float* s = srcA + mbase + 128;
#pragma unroll
      for (int k = 0; k < 4; k++) cp16(fm_base + dstA + k*16, s + k*4);
      CP_COMMIT();
      CP_WAIT1();                    // half B of tile mt ready
    } else {
      CP_WAIT0();
    }
    __syncthreads();

    // ---- gram over c-half B (c 32..63) ----
#pragma unroll 4
    for (int c = 32; c < 64; c++){
      const ulonglong2* fp = (const ulonglong2*)(fnT2 + c*64 + r0);
      ulonglong2 fA = fp[0], fB = fp[1], fC = fp[2], fD = fp[3];
      ulonglong2 mm = *(const ulonglong2*)(fmT + c*128 + (lane<<2));
      ffma2(acc[0][0], fA.x, mm.x); ffma2(acc[0][1], fA.x, mm.y);
      ffma2(acc[1][0], fA.y, mm.x); ffma2(acc[1][1], fA.y, mm.y);
      ffma2(acc[2][0], fB.x, mm.x); ffma2(acc[2][1], fB.x, mm.y);
      ffma2(acc[3][0], fB.y, mm.x); ffma2(acc[3][1], fB.y, mm.y);
      ffma2(acc[4][0], fC.x, mm.x); ffma2(acc[4][1], fC.x, mm.y);
      ffma2(acc[5][0], fC.y, mm.x); ffma2(acc[5][1], fC.y, mm.y);
      ffma2(acc[6][0], fD.x, mm.x); ffma2(acc[6][1], fD.x, mm.y);
      ffma2(acc[7][0], fD.y, mm.x); ffma2(acc[7][1], fD.y, mm.y);
    }

    // ---- stream direct rows + mirrored transpose ----
    {
      float va0[8], va1[8], va2[8], va3[8];
#pragma unroll
      for (int i = 0; i < 8; i++){
        float2 dA = unpk(acc[i][0]);
        float2 dB = unpk(acc[i][1]);
        *(float4*)(scb + (size_t)(nbase + r0 + i)*NN + mbase + (lane<<2))
            = make_float4(dA.x, dA.y, dB.x, dB.y);
        va0[i] = dA.x; va1[i] = dA.y; va2[i] = dB.x; va3[i] = dB.y;
      }
      int mrow = mbase + (lane<<2);
      float* mp0 = scb + (size_t)(mrow  )*NN + nbase + r0;
      float* mp1 = scb + (size_t)(mrow+1)*NN + nbase + r0;
      float* mp2 = scb + (size_t)(mrow+2)*NN + nbase + r0;
      float* mp3 = scb + (size_t)(mrow+3)*NN + nbase + r0;
      *(float4*)(mp0)   = make_float4(va0[0], va0[1], va0[2], va0[3]);
      *(float4*)(mp0+4) = make_float4(va0[4], va0[5], va0[6], va0[7]);
      *(float4*)(mp1)   = make_float4(va1[0], va1[1], va1[2], va1[3]);
      *(float4*)(mp1+4) = make_float4(va1[4], va1[5], va1[6], va1[7]);
      *(float4*)(mp2)   = make_float4(va2[0], va2[1], va2[2], va2[3]);
      *(float4*)(mp2+4) = make_float4(va2[4], va2[5], va2[6], va2[7]);
      *(float4*)(mp3)   = make_float4(va3[0], va3[1], va3[2], va3[3]);
      *(float4*)(mp3+4) = make_float4(va3[4], va3[5], va3[6], va3[7]);
    }
    __syncthreads();                 // readers of half B done

    if (mt < 31){                    // refill half B with tile mt+1
      const float* s = srcB + mbase + 128;
#pragma unroll
      for (int k = 0; k < 4; k++) cp16(fm_base + dstB + k*16, s + k*4);
      CP_COMMIT();
      CP_WAIT1();                    // half A of tile mt+1 ready
      __syncthreads();
    }
  }
}

// -------------------- 3b. topk: one warp per row, prefetched stream -------------
__global__ __launch_bounds__(256) void topk_kernel(){
  int tid = threadIdx.x;
  int lane = tid & 31, wid = tid >> 5;
  int row = blockIdx.x * 8 + wid;
  int b = row >> 12;
  const float4* srow = (const float4*)(g_scores + (size_t)row*NN);
  const float4* sqr  = (const float4*)(g_sqn + (size_t)b*NN);

  unsigned cur_lo = (unsigned)lane; int cur_idx = 0; unsigned thr = 0u;

  float4 g  = srow[lane];
  float4 sq = sqr [lane];

  for (int mt = 0; mt < 32; mt++){
    unsigned u0 = ofix(fmaf(2.f, g.x, -sq.x));
    unsigned u1 = ofix(fmaf(2.f, g.y, -sq.y));
    unsigned u2 = ofix(fmaf(2.f, g.z, -sq.z));
    unsigned u3 = ofix(fmaf(2.f, g.w, -sq.w));
    // prefetch next tile before the (variable-latency) merge loops
    if (mt < 31){
      g  = srow[(mt+1)*32 + lane];
      sq = sqr [(mt+1)*32 + lane];
    }

    if (mt == 0){
      unsigned m01 = max(u0, u1), m23 = max(u2, u3);
      unsigned um4 = max(m01, m23);
      int jm = (um4 == u0) ? 0 : (um4 == u1) ? 1 : (um4 == u2) ? 2 : 3;
      cur_lo  = (um4 & ~31u) | (unsigned)lane;
      cur_idx = (lane<<2) + jm;
      thr = __reduce_min_sync(FULLMASK, cur_lo);
      if (jm == 0) u0 = 0u; else if (jm == 1) u1 = 0u;
      else if (jm == 2) u2 = 0u; else u3 = 0u;
    }

    unsigned um = max(max(u0,u1), max(u2,u3));
    if (!__any_sync(FULLMASK, um > thr)) continue;
    unsigned uu[4] = {u0,u1,u2,u3};
#pragma unroll
    for (int j=0;j<4;j++){
      unsigned cu = uu[j];
      int      ci = mt*128 + (lane<<2) + j;
      unsigned mask = __ballot_sync(FULLMASK, cu > thr);
      while (mask){
        int src = __ffs(mask) - 1; mask &= mask - 1;
        unsigned c_u = __shfl_sync(FULLMASK, cu, src);
        int      c_i = __shfl_sync(FULLMASK, ci, src);
        unsigned mp = __reduce_min_sync(FULLMASK, cur_lo);
        if (c_u > mp){
          if (lane == (int)(mp & 31u)){ cur_lo = (c_u & ~31u) | (unsigned)lane; cur_idx = c_i; }
          thr = mp;   // lazy lower bound (pre-insertion min)
        }
      }
    }
  }
  g_knn[(size_t)row*KK + lane] = cur_idx;
}

// -------------------- 4. factorized attention + fused BN1 stats ------------------
#define AT_WARPS 16
#define AT_WBUF 2688
#define DIFF_LD 68

__global__ __launch_bounds__(512) void attn_kernel(const float* __restrict__ wq,
                                                   const float* __restrict__ wk,
                                                   const float* __restrict__ wv){
  extern __shared__ float smf[];
  float2* wq2 = (float2*)smf;
  float2* wv2 = wq2 + 2048;
  float2* wk2 = wv2 + 2048;
  int tid = threadIdx.x;
  int lane = tid & 31, wid = tid >> 5;
  float* wb    = smf + 12288 + wid*AT_WBUF;
  float* sdiff = wb;
  float* sfn   = wb + 2176;
  float* sq    = wb + 2240;
  float* sqk   = wb + 2304;
  float* sattn = wb + 2560;
  float* swd   = sqk;

  for (int idx = tid; idx < 2048; idx += 512){
    int cc = idx >> 5, oo = idx & 31;
    wq2[idx] = make_float2(wq[oo*64 + cc], wq[(oo+32)*64 + cc]);
    wv2[idx] = make_float2(wv[oo*64 + cc], wv[(oo+32)*64 + cc]);
    int o = idx >> 5, c = idx & 31;
    wk2[idx] = make_float2(wk[o*64 + c], wk[o*64 + c + 32]);
  }
  __syncthreads();

  int rowbase = blockIdx.x * (AT_WARPS*4);
  float s0 = 0.f, q0s = 0.f, s1 = 0.f, q1s = 0.f;   // BN1 partials

  for (int rr = 0; rr < 4; rr++){
    int row = rowbase + wid*4 + rr;
    int b = row >> 12;

    sfn[lane]      = g_feat[(size_t)row*CC + lane];
    sfn[lane + 32] = g_feat[(size_t)row*CC + lane + 32];
    __syncwarp();

    {
      int nbr = g_knn[(size_t)row*KK + lane];
      const float4* frow = (const float4*)(g_feat + ((size_t)(b<<12) + nbr)*CC);
      float4* drow = (float4*)(sdiff + lane*DIFF_LD);
#pragma unroll
      for (int c4 = 0; c4 < 16; c4++){
        float4 v = frow[c4];
        float4 f = *(const float4*)(sfn + c4*4);
        drow[c4] = make_float4(v.x-f.x, v.y-f.y, v.z-f.z, v.w-f.w);
      }
    }

    {
      float q0 = 0.f, q1 = 0.f;
#pragma unroll
      for (int c4 = 0; c4 < 16; c4++){
        float4 f = *(const float4*)(sfn + c4*4);
        float2 w0 = wq2[(c4*4  )*32 + lane];
        float2 w1 = wq2[(c4*4+1)*32 + lane];
        float2 w2 = wq2[(c4*4+2)*32 + lane];
        float2 w3 = wq2[(c4*4+3)*32 + lane];
        q0 += f.x*w0.x + f.y*w1.x + f.z*w2.x + f.w*w3.x;
        q1 += f.x*w0.y + f.y*w1.y + f.z*w2.y + f.w*w3.y;
      }
      sq[lane] = q0; sq[lane+32] = q1;
    }
    __syncwarp();

    {
      float a[8];
#pragma unroll
      for (int t=0;t<8;t++) a[t]=0.f;
#pragma unroll
      for (int o = 0; o < 64; o++){
        int h = o >> 4;
        float qb = sq[o];
        float2 w = wk2[o*32 + lane];
        a[h*2  ] += qb*w.x;
        a[h*2+1] += qb*w.y;
      }
#pragma unroll
      for (int h=0;h<4;h++){
        sqk[h*64 + lane]      = a[h*2];
        sqk[h*64 + lane + 32] = a[h*2+1];
      }
    }
    __syncwarp();

    {
      float e0=0.f,e1=0.f,e2=0.f,e3=0.f;
      const float4* drow = (const float4*)(sdiff + lane*DIFF_LD);
#pragma unroll
      for (int c4 = 0; c4 < 16; c4++){
        float4 d = drow[c4];
        float4 k0 = *(const float4*)(sqk + 0*64 + c4*4);
        float4 k1 = *(const float4*)(sqk + 1*64 + c4*4);
        float4 k2 = *(const float4*)(sqk + 2*64 + c4*4);
        float4 k3 = *(const float4*)(sqk + 3*64 + c4*4);
        e0 += d.x*k0.x + d.y*k0.y + d.z*k0.z + d.w*k0.w;
        e1 += d.x*k1.x + d.y*k1.y + d.z*k1.z + d.w*k1.w;
        e2 += d.x*k2.x + d.y*k2.y + d.z*k2.z + d.w*k2.w;
        e3 += d.x*k3.x + d.y*k3.y + d.z*k3.z + d.w*k3.w;
      }
      float e[4] = {e0*0.25f, e1*0.25f, e2*0.25f, e3*0.25f};
      float a[4];
#pragma unroll
      for (int h=0;h<4;h++){
        float mx = warp_max32(e[h]);
        float ex = __expf(e[h]-mx);
        float s  = warp_sum32(ex);
        a[h] = ex / s;
      }
      *(float4*)(sattn + lane*4) = make_float4(a[0],a[1],a[2],a[3]);
    }
    __syncwarp();

    {
      float w[8];
#pragma unroll
      for (int t=0;t<8;t++) w[t]=0.f;
#pragma unroll
      for (int k = 0; k < 32; k++){
        float4 at = *(const float4*)(sattn + k*4);
        float d0 = sdiff[k*DIFF_LD + lane];
        float d1 = sdiff[k*DIFF_LD + lane + 32];
        w[0]+=at.x*d0; w[1]+=at.x*d1;
        w[2]+=at.y*d0; w[3]+=at.y*d1;
        w[4]+=at.z*d0; w[5]+=at.z*d1;
        w[6]+=at.w*d0; w[7]+=at.w*d1;
      }
      __syncwarp();
#pragma unroll
      for (int h=0;h<4;h++){
        swd[h*64 + lane]      = w[h*2];
        swd[h*64 + lane + 32] = w[h*2+1];
      }
    }
    __syncwarp();

    {
      int h0 = lane >> 4;
      float o0 = 0.f, o1 = 0.f;
#pragma unroll
      for (int c4 = 0; c4 < 16; c4++){
        float4 d0 = *(const float4*)(swd + h0*64     + c4*4);
        float4 d1 = *(const float4*)(swd + (h0+2)*64 + c4*4);
        float2 w0 = wv2[(c4*4  )*32 + lane];
        float2 w1 = wv2[(c4*4+1)*32 + lane];
        float2 w2 = wv2[(c4*4+2)*32 + lane];
        float2 w3 = wv2[(c4*4+3)*32 + lane];
        o0 += d0.x*w0.x + d0.y*w1.x + d0.z*w2.x + d0.w*w3.x;
        o1 += d1.x*w0.y + d1.y*w1.y + d1.z*w2.y + d1.w*w3.y;
      }
      float f00 = sfn[lane]      + o0;
      float f01 = sfn[lane + 32] + o1;
      g_f0[(size_t)row*CC + lane]      = f00;
      g_f0[(size_t)row*CC + lane + 32] = f01;
      s0 += f00; q0s += f00*f00;
      s1 += f01; q1s += f01*f01;
    }
    __syncwarp();
  }

  // fused BN1 stats
  __syncthreads();
  float2* sc0 = (float2*)smf;
  float2* sc1 = sc0 + 512;
  sc0[wid*32 + lane] = make_float2(s0, q0s);
  sc1[wid*32 + lane] = make_float2(s1, q1s);
  __syncthreads();
  if (tid < 64){
    const float2* srcp = (tid < 32) ? (sc0 + tid) : (sc1 + (tid - 32));
    float s = 0.f, q = 0.f;
#pragma unroll
    for (int w = 0; w < 16; w++){ float2 v = srcp[w*32]; s += v.x; q += v.y; }
    g_psum[blockIdx.x*64 + tid] = s;
    g_psq [blockIdx.x*64 + tid] = q;
  }
}

// -------------------- 5. BN finalize (512 partials) --------------------
__global__ void bn_finalize_kernel(){
  __shared__ float ps[256], pq[256];
  int c = threadIdx.x & 63, part = threadIdx.x >> 6;
  float s = 0.f, q = 0.f;
  for (int i = part; i < 512; i += 4){ s += g_psum[i*64 + c]; q += g_psq[i*64 + c]; }
  ps[threadIdx.x] = s; pq[threadIdx.x] = q;
  __syncthreads();
  if (threadIdx.x < 64){
    s = ps[c] + ps[c+64] + ps[c+128] + ps[c+192];
    q = pq[c] + pq[c+64] + pq[c+128] + pq[c+192];
    float m   = s * (1.f/32768.f);
    float var = q * (1.f/32768.f) - m*m;
    g_mu[c] = m;
    g_rs[c] = rsqrtf(var + 1e-5f);
  }
}

// -------------------- 6a. MLP layer 1: BN1-normalize + w1 + LeakyReLU ----------
#define MLP1_SMEM ((16384 + 256)*4)
__global__ __launch_bounds__(256,3) void mlp1_kernel(const float* __restrict__ w1,
                                                     const float* __restrict__ g1,
                                                     const float* __restrict__ b1){
  extern __shared__ float smf[];
  float* w1T  = smf;              // [c][o] 64x256
  float* sf1T = smf + 16384;      // [c][j] 64x4
  __shared__ float ssc[64], ssh[64];
  int tid = threadIdx.x;

  {
    int o = tid;
#pragma unroll
    for (int c4 = 0; c4 < 16; c4++){
      float4 v = *(const float4*)(w1 + o*64 + c4*4);
      int c = c4*4;
      w1T[c*256+o]=v.x; w1T[(c+1)*256+o]=v.y; w1T[(c+2)*256+o]=v.z; w1T[(c+3)*256+o]=v.w;
    }
  }
  if (tid < 64){
    float r = g_rs[tid] * g1[tid];
    ssc[tid] = r;
    ssh[tid] = b1[tid] - g_mu[tid]*r;
  }
  __syncthreads();

  int rowbase = blockIdx.x * 64;
  for (int it = 0; it < 16; it++){
    int row0 = rowbase + it*4;
    {
      int c = tid >> 2, j = tid & 3;
      sf1T[tid] = g_f0[(size_t)(row0+j)*CC + c]*ssc[c] + ssh[c];
    }
    __syncthreads();
    float h0=0.f,h1=0.f,h2=0.f,h3=0.f;
#pragma unroll
    for (int c = 0; c < 64; c++){
      float w = w1T[c*256 + tid];
      float4 f = *(const float4*)(sf1T + c*4);
      h0+=f.x*w; h1+=f.y*w; h2+=f.z*w; h3+=f.w*w;
    }
    h0 = (h0>0.f)?h0:0.2f*h0; h1 = (h1>0.f)?h1:0.2f*h1;
    h2 = (h2>0.f)?h2:0.2f*h2; h3 = (h3>0.f)?h3:0.2f*h3;
    g_hid[(size_t)(row0+0)*256 + tid] = h0;
    g_hid[(size_t)(row0+1)*256 + tid] = h1;
    g_hid[(size_t)(row0+2)*256 + tid] = h2;
    g_hid[(size_t)(row0+3)*256 + tid] = h3;
    __syncthreads();
  }
}

// -------------------- 6b. MLP layer 2: w2 + residual + fused BN2 stats ----------
#define MLP2_SMEM ((16384 + 1024 + 256 + 1024)*4)
__global__ __launch_bounds__(256,3) void mlp2_kernel(const float* __restrict__ w2,
                                                     const float* __restrict__ g1,
                                                     const float* __restrict__ b1){
  extern __shared__ float smf[];
  float* w2T   = smf;              // [o][c] 256x64
  float* shT   = smf + 16384;      // [o][j] 256x4
  float* sf1T  = smf + 17408;      // [c][j] 64x4
  float* spart = smf + 17664;      // 1024
  __shared__ float ssc[64], ssh[64];
  int tid = threadIdx.x;

  {
    int c = tid & 63, o4b = tid >> 6;
#pragma unroll
    for (int it = 0; it < 16; it++){
      int o2 = (o4b + 4*it) * 4;
      float4 v = *(const float4*)(w2 + c*256 + o2);
      w2T[o2*64+c]=v.x; w2T[(o2+1)*64+c]=v.y; w2T[(o2+2)*64+c]=v.z; w2T[(o2+3)*64+c]=v.w;
    }
  }
  if (tid < 64){
    float r = g_rs[tid] * g1[tid];
    ssc[tid] = r;
    ssh[tid] = b1[tid] - g_mu[tid]*r;
  }
  __syncthreads();

  int rowbase = blockIdx.x * 64;
  float s_loc = 0.f, q_loc = 0.f;
  for (int it = 0; it < 16; it++){
    int row0 = rowbase + it*4;
    {
      int c = tid >> 2, j = tid & 3;
      sf1T[tid] = g_f0[(size_t)(row0+j)*CC + c]*ssc[c] + ssh[c];
    }
#pragma unroll
    for (int j = 0; j < 4; j++)
      shT[tid*4 + j] = g_hid[(size_t)(row0+j)*256 + tid];
    __syncthreads();
    {
      int c = tid & 63, part = tid >> 6;
      float p0=0.f,p1=0.f,p2=0.f,p3=0.f;
#pragma unroll
      for (int oo = 0; oo < 64; oo++){
        int o = part*64 + oo;
        float w = w2T[o*64 + c];
        float4 hv = *(const float4*)(shT + o*4);
        p0+=hv.x*w; p1+=hv.y*w; p2+=hv.z*w; p3+=hv.w*w;
      }
      spart[(0*4+part)*64 + c] = p0;
      spart[(1*4+part)*64 + c] = p1;
      spart[(2*4+part)*64 + c] = p2;
      spart[(3*4+part)*64 + c] = p3;
    }
    __syncthreads();
    {
      int c = tid & 63, j = tid >> 6;
      float ff = spart[(j*4+0)*64+c] + spart[(j*4+1)*64+c]
               + spart[(j*4+2)*64+c] + spart[(j*4+3)*64+c];
      float v = sf1T[c*4+j] + ff;
      g_f2[(size_t)(row0+j)*CC + c] = v;
      s_loc += v; q_loc += v*v;
    }
    __syncthreads();
  }

  {
    int c = tid & 63, j = tid >> 6;
    spart[j*64 + c]       = s_loc;
    spart[(4+j)*64 + c]   = q_loc;
  }
  __syncthreads();
  if (tid < 64){
    float s = spart[tid] + spart[64+tid] + spart[128+tid] + spart[192+tid];
    float q = spart[256+tid] + spart[320+tid] + spart[384+tid] + spart[448+tid];
    g_psum[blockIdx.x*64 + tid] = s;
    g_psq [blockIdx.x*64 + tid] = q;
  }
}

// -------------------- 7. BN2-normalize + transpose to (B,C,N) --------------------
__global__ void out_kernel(const float* __restrict__ g2, const float* __restrict__ b2,
                           float* __restrict__ out){
  __shared__ float tile[32][33];
  int b  = blockIdx.z;
  int c0 = blockIdx.y * 32;
  int n0 = blockIdx.x * 32;
  int tx = threadIdx.x, ty = threadIdx.y;
  const float* fb = g_f2 + (size_t)b*NN*CC;
#pragma unroll
  for (int i = 0; i < 32; i += 8)
    tile[ty+i][tx] = fb[(size_t)(n0+ty+i)*CC + c0 + tx];
  __syncthreads();
#pragma unroll
  for (int i = 0; i < 32; i += 8){
    int c = c0 + ty + i;
    float sc = g_rs[c]*g2[c];
    float sh = b2[c] - g_mu[c]*sc;
    out[((size_t)b*CC + c)*NN + n0 + tx] = tile[tx][ty+i]*sc + sh;
  }
}

// -------------------- launch --------------------
extern "C" void kernel_launch(void* const* d_in, const int* in_sizes, int n_in,
                              void* d_out, int out_size){
  (void)in_sizes; (void)n_in; (void)out_size;
  const float* x  = (const float*)d_in[0];
  const float* wq = (const float*)d_in[1];
  const float* wk = (const float*)d_in[2];
  const float* wv = (const float*)d_in[3];
  const float* w1 = (const float*)d_in[4];
  const float* w2 = (const float*)d_in[5];
  const float* g1 = (const float*)d_in[6];
  const float* b1 = (const float*)d_in[7];
  const float* g2 = (const float*)d_in[8];
  const float* b2 = (const float*)d_in[9];
  float* out = (float*)d_out;

  const int ATTN_SMEM = (12288 + AT_WARPS*AT_WBUF) * 4;
  cudaFuncSetAttribute(gram_kernel, cudaFuncAttributeMaxDynamicSharedMemorySize, KNN_SMEM_BYTES);
  cudaFuncSetAttribute(attn_kernel, cudaFuncAttributeMaxDynamicSharedMemorySize, ATTN_SMEM);
  cudaFuncSetAttribute(mlp1_kernel, cudaFuncAttributeMaxDynamicSharedMemorySize, MLP1_SMEM);
  cudaFuncSetAttribute(mlp2_kernel, cudaFuncAttributeMaxDynamicSharedMemorySize, MLP2_SMEM);

  transpose_kernel<<<dim3(NN/32, CC/32, BB), dim3(32,8)>>>(x);
  sqnorm_kernel<<<ROWS/256, 256>>>();
  gram_kernel<<<dim3(NN/64, BB), 256, KNN_SMEM_BYTES>>>(x);
  topk_kernel<<<ROWS/8, 256>>>();
  attn_kernel<<<ROWS/(AT_WARPS*4), 512, ATTN_SMEM>>>(wq, wk, wv);
  bn_finalize_kernel<<<1, 256>>>();
  mlp1_kernel<<<ROWS/64, 256, MLP1_SMEM>>>(w1, g1, b1);
  mlp2_kernel<<<ROWS/64, 256, MLP2_SMEM>>>(w2, g1, b1);
  bn_finalize_kernel<<<1, 256>>>();
  out_kernel<<<dim3(NN/32, CC/32, BB), dim3(32,8)>>>(g2, b2, out);
}

// round 17
// speedup vs baseline: 1.6338x; 1.0630x over previous
#include <cuda_runtime.h>
#include <cuda_bf16.h>
#include <float.h>
#include <cstdint>

// Problem constants
#define BB 8
#define CC 64
#define NN 4096
#define KK 32
#define HH 4
#define DD 16
#define ROWS (BB*NN)          // 32768
#define FULLMASK 0xffffffffu

// -------------------- device scratch --------------------
__device__ float g_feat[ROWS*CC];   // (B,N,C) fp32
__device__ float g_sqn[ROWS];       // squared norms
__device__ float g_scores[(size_t)ROWS*NN];  // raw Gram dots (536 MB)
__device__ int   g_knn[ROWS*KK];    // top-K indices (in-batch n)
__device__ float g_f0[ROWS*CC];     // feat + attention out
__device__ float g_hid[(size_t)ROWS*256];    // MLP hidden (33.5 MB)
__device__ float g_f2[ROWS*CC];     // f1 + ff (pre-BN2)
__device__ float g_psum[512*CC];    // per-block BN partial sums
__device__ float g_psq[512*CC];
__device__ float g_mu[CC];
__device__ float g_rs[CC];

// -------------------- warp helpers --------------------
__device__ __forceinline__ float warp_max32(float v){
#pragma unroll
  for (int o=16;o>0;o>>=1) v = fmaxf(v, __shfl_xor_sync(FULLMASK, v, o));
  return v;
}
__device__ __forceinline__ float warp_sum32(float v){
#pragma unroll
  for (int o=16;o>0;o>>=1) v += __shfl_xor_sync(FULLMASK, v, o);
  return v;
}
// packed f32x2 FMA (Blackwell native; ptxas won't auto-fuse)
__device__ __forceinline__ void ffma2(unsigned long long& d, unsigned long long a,
                                      unsigned long long b){
  asm("fma.rn.f32x2 %0, %1, %2, %0;" : "+l"(d) : "l"(a), "l"(b));
}
__device__ __forceinline__ float2 unpk(unsigned long long v){
  float2 r; asm("mov.b64 {%0, %1}, %2;" : "=f"(r.x), "=f"(r.y) : "l"(v));
  return r;
}
// order-preserving float->uint transform
__device__ __forceinline__ unsigned ofix(float v){
  unsigned u = __float_as_uint(v);
  return (u & 0x80000000u) ? ~u : (u | 0x80000000u);
}
// cp.async 16B
__device__ __forceinline__ void cp16(uint32_t dst, const void* src){
  asm volatile("cp.async.cg.shared.global [%0], [%1], 16;" :: "r"(dst), "l"(src));
}
#define CP_COMMIT() asm volatile("cp.async.commit_group;" ::: "memory")
#define CP_WAIT1()  asm volatile("cp.async.wait_group 1;" ::: "memory")
#define CP_WAIT0()  asm volatile("cp.async.wait_group 0;" ::: "memory")
__device__ __forceinline__ uint32_t smem_u32(const void* p){
  uint32_t a;
  asm("{ .reg .u64 t; cvta.to.shared.u64 t, %1; cvt.u32.u64 %0, t; }" : "=r"(a) : "l"(p));
  return a;
}

// -------------------- 1. transpose x (B,C,N) -> feat (B,N,C) --------------------
__global__ void transpose_kernel(const float* __restrict__ x){
  __shared__ float tile[32][33];
  int b  = blockIdx.z;
  int c0 = blockIdx.y * 32;
  int n0 = blockIdx.x * 32;
  int tx = threadIdx.x, ty = threadIdx.y;   // (32,8)
  const float* xb = x + (size_t)b*CC*NN;
#pragma unroll
  for (int i = 0; i < 32; i += 8)
    tile[ty+i][tx] = xb[(size_t)(c0+ty+i)*NN + n0 + tx];
  __syncthreads();
  float* fb = g_feat + (size_t)b*NN*CC;
#pragma unroll
  for (int i = 0; i < 32; i += 8)
    fb[(size_t)(n0+ty+i)*CC + c0 + tx] = tile[tx][ty+i];
}

// -------------------- 2. squared norms --------------------
__global__ void sqnorm_kernel(){
  int row = blockIdx.x*blockDim.x + threadIdx.x;
  if (row >= ROWS) return;
  const float4* f = (const float4*)(g_feat + (size_t)row*CC);
  float s = 0.f;
#pragma unroll
  for (int i=0;i<16;i++){ float4 v=f[i]; s += v.x*v.x+v.y*v.y+v.z*v.z+v.w*v.w; }
  g_sqn[row] = s;
}

// -------------------- 3a. symmetric Gram: upper triangle + mirrored writes ------
#define KNN_SMEM_BYTES ((8192*2)*4)

__global__ __launch_bounds__(256,3) void gram_kernel(const float* __restrict__ x){
  extern __shared__ float sm[];
  float2* fnT2 = (float2*)sm;          // [c][r] duplicated {v,v}
  float*  fmT  = sm + 8192;            // [c][m]  (c0-31 = half A, c32-63 = half B)

  int b = blockIdx.y;
  int rb = blockIdx.x;                 // row-tile index 0..63
  int nbase = rb * 64;
  int tstart = rb >> 1;                // first m-tile (128-wide)
  const float* fb = g_feat + (size_t)b*NN*CC;
  const float* xb = x + (size_t)b*CC*NN;
  int tid = threadIdx.x;
  int lane = tid & 31, wid = tid >> 5;
  int r0 = wid * 8;

  uint32_t fm_base = smem_u32(fmT);

  int lc   = tid >> 3;
  int lseg = tid & 7;
  const float* srcA = xb + (size_t)lc*NN      + lseg*16;
  const float* srcB = xb + (size_t)(lc+32)*NN + lseg*16;
  uint32_t     dstA = (uint32_t)((lc*128      + lseg*16)*4);
  uint32_t     dstB = (uint32_t)(((lc+32)*128 + lseg*16)*4);

  // prologue: issue first tile halves as two groups
  {
    const float* pA = srcA + tstart*128;
    const float* pB = srcB + tstart*128;
#pragma unroll
    for (int k = 0; k < 4; k++) cp16(fm_base + dstA + k*16, pA + k*4);
    CP_COMMIT();
#pragma unroll
    for (int k = 0; k < 4; k++) cp16(fm_base + dstB + k*16, pB + k*4);
    CP_COMMIT();
  }

  // load fnT2 (64 rows) transposed + duplicated (from row-major g_feat)
  {
    int r = tid & 63, cg = tid >> 6;     // cg 0..3
#pragma unroll
    for (int it = 0; it < 4; it++){
      int c = (cg + it*4) * 4;
      float4 v = *(const float4*)(fb + (size_t)(nbase + r)*CC + c);
      fnT2[(c  )*64 + r] = make_float2(v.x, v.x);
      fnT2[(c+1)*64 + r] = make_float2(v.y, v.y);
      fnT2[(c+2)*64 + r] = make_float2(v.z, v.z);
      fnT2[(c+3)*64 + r] = make_float2(v.w, v.w);
    }
  }

  CP_WAIT1();          // half A of first tile ready
  __syncthreads();

  float* scb = g_scores + (size_t)b*NN*NN;

  for (int mt = tstart; mt < 32; mt++){
    int mbase = mt * 128;

    unsigned long long acc[8][2];
#pragma unroll
    for (int i=0;i<8;i++){ acc[i][0]=0ull; acc[i][1]=0ull; }

    // ---- gram over c-half A (c 0..31) ----
#pragma unroll 4
    for (int c = 0; c < 32; c++){
      const ulonglong2* fp = (const ulonglong2*)(fnT2 + c*64 + r0);
      ulonglong2 fA = fp[0], fB = fp[1], fC = fp[2], fD = fp[3];
      ulonglong2 mm = *(const ulonglong2*)(fmT + c*128 + (lane<<2));
      ffma2(acc[0][0], fA.x, mm.x); ffma2(acc[0][1], fA.x, mm.y);
      ffma2(acc[1][0], fA.y, mm.x); ffma2(acc[1][1], fA.y, mm.y);
      ffma2(acc[2][0], fB.x, mm.x); ffma2(acc[2][1], fB.x, mm.y);
      ffma2(acc[3][0], fB.y, mm.x); ffma2(acc[3][1], fB.y, mm.y);
      ffma2(acc[4][0], fC.x, mm.x); ffma2(acc[4][1], fC.x, mm.y);
      ffma2(acc[5][0], fC.y, mm.x); ffma2(acc[5][1], fC.y, mm.y);
      ffma2(acc[6][0], fD.x, mm.x); ffma2(acc[6][1], fD.x, mm.y);
      ffma2(acc[7][0], fD.y, mm.x); ffma2(acc[7][1], fD.y, mm.y);
    }
    __syncthreads();                 // all readers of half A done

    if (mt < 31){                    // refill half A with tile mt+1
      const float* s = srcA + mbase + 128;
#pragma unroll
      for (int k = 0; k < 4; k++) cp16(fm_base + dstA + k*16, s + k*4);
      CP_COMMIT();
      CP_WAIT1();                    // half B of tile mt ready
    } else {
      CP_WAIT0();
    }
    __syncthreads();

    // ---- gram over c-half B (c 32..63) ----
#pragma unroll 4
    for (int c = 32; c < 64; c++){
      const ulonglong2* fp = (const ulonglong2*)(fnT2 + c*64 + r0);
      ulonglong2 fA = fp[0], fB = fp[1], fC = fp[2], fD = fp[3];
      ulonglong2 mm = *(const ulonglong2*)(fmT + c*128 + (lane<<2));
      ffma2(acc[0][0], fA.x, mm.x); ffma2(acc[0][1], fA.x, mm.y);
      ffma2(acc[1][0], fA.y, mm.x); ffma2(acc[1][1], fA.y, mm.y);
      ffma2(acc[2][0], fB.x, mm.x); ffma2(acc[2][1], fB.x, mm.y);
      ffma2(acc[3][0], fB.y, mm.x); ffma2(acc[3][1], fB.y, mm.y);
      ffma2(acc[4][0], fC.x, mm.x); ffma2(acc[4][1], fC.x, mm.y);
      ffma2(acc[5][0], fC.y, mm.x); ffma2(acc[5][1], fC.y, mm.y);
      ffma2(acc[6][0], fD.x, mm.x); ffma2(acc[6][1], fD.x, mm.y);
      ffma2(acc[7][0], fD.y, mm.x); ffma2(acc[7][1], fD.y, mm.y);
    }

    // ---- stream direct rows + mirrored transpose ----
    {
      float va0[8], va1[8], va2[8], va3[8];
#pragma unroll
      for (int i = 0; i < 8; i++){
        float2 dA = unpk(acc[i][0]);
        float2 dB = unpk(acc[i][1]);
        *(float4*)(scb + (size_t)(nbase + r0 + i)*NN + mbase + (lane<<2))
            = make_float4(dA.x, dA.y, dB.x, dB.y);
        va0[i] = dA.x; va1[i] = dA.y; va2[i] = dB.x; va3[i] = dB.y;
      }
      int mrow = mbase + (lane<<2);
      float* mp0 = scb + (size_t)(mrow  )*NN + nbase + r0;
      float* mp1 = scb + (size_t)(mrow+1)*NN + nbase + r0;
      float* mp2 = scb + (size_t)(mrow+2)*NN + nbase + r0;
      float* mp3 = scb + (size_t)(mrow+3)*NN + nbase + r0;
      *(float4*)(mp0)   = make_float4(va0[0], va0[1], va0[2], va0[3]);
      *(float4*)(mp0+4) = make_float4(va0[4], va0[5], va0[6], va0[7]);
      *(float4*)(mp1)   = make_float4(va1[0], va1[1], va1[2], va1[3]);
      *(float4*)(mp1+4) = make_float4(va1[4], va1[5], va1[6], va1[7]);
      *(float4*)(mp2)   = make_float4(va2[0], va2[1], va2[2], va2[3]);
      *(float4*)(mp2+4) = make_float4(va2[4], va2[5], va2[6], va2[7]);
      *(float4*)(mp3)   = make_float4(va3[0], va3[1], va3[2], va3[3]);
      *(float4*)(mp3+4) = make_float4(va3[4], va3[5], va3[6], va3[7]);
    }
    __syncthreads();                 // readers of half B done

    if (mt < 31){                    // refill half B with tile mt+1
      const float* s = srcB + mbase + 128;
#pragma unroll
      for (int k = 0; k < 4; k++) cp16(fm_base + dstB + k*16, s + k*4);
      CP_COMMIT();
      CP_WAIT1();                    // half A of tile mt+1 ready
      __syncthreads();
    }
  }
}

// -------------------- 3b. topk: one warp per row, prefetched stream -------------
__global__ __launch_bounds__(256,7) void topk_kernel(){
  int tid = threadIdx.x;
  int lane = tid & 31, wid = tid >> 5;
  int row = blockIdx.x * 8 + wid;
  int b = row >> 12;
  const float4* srow = (const float4*)(g_scores + (size_t)row*NN);
  const float4* sqr  = (const float4*)(g_sqn + (size_t)b*NN);

  unsigned cur_lo = (unsigned)lane; int cur_idx = 0; unsigned thr = 0u;

  float4 g  = srow[lane];
  float4 sq = sqr [lane];

  for (int mt = 0; mt < 32; mt++){
    unsigned u0 = ofix(fmaf(2.f, g.x, -sq.x));
    unsigned u1 = ofix(fmaf(2.f, g.y, -sq.y));
    unsigned u2 = ofix(fmaf(2.f, g.z, -sq.z));
    unsigned u3 = ofix(fmaf(2.f, g.w, -sq.w));
    // prefetch next tile before the (variable-latency) merge loops
    if (mt < 31){
      g  = srow[(mt+1)*32 + lane];
      sq = sqr [(mt+1)*32 + lane];
    }

    if (mt == 0){
      unsigned m01 = max(u0, u1), m23 = max(u2, u3);
      unsigned um4 = max(m01, m23);
      int jm = (um4 == u0) ? 0 : (um4 == u1) ? 1 : (um4 == u2) ? 2 : 3;
      cur_lo  = (um4 & ~31u) | (unsigned)lane;
      cur_idx = (lane<<2) + jm;
      thr = __reduce_min_sync(FULLMASK, cur_lo);
      if (jm == 0) u0 = 0u; else if (jm == 1) u1 = 0u;
      else if (jm == 2) u2 = 0u; else u3 = 0u;
    }

    unsigned um = max(max(u0,u1), max(u2,u3));
    if (!__any_sync(FULLMASK, um > thr)) continue;
    unsigned uu[4] = {u0,u1,u2,u3};
#pragma unroll
    for (int j=0;j<4;j++){
      unsigned cu = uu[j];
      int      ci = mt*128 + (lane<<2) + j;
      unsigned mask = __ballot_sync(FULLMASK, cu > thr);
      while (mask){
        int src = __ffs(mask) - 1; mask &= mask - 1;
        unsigned c_u = __shfl_sync(FULLMASK, cu, src);
        int      c_i = __shfl_sync(FULLMASK, ci, src);
        unsigned mp = __reduce_min_sync(FULLMASK, cur_lo);
        if (c_u > mp){
          if (lane == (int)(mp & 31u)){ cur_lo = (c_u & ~31u) | (unsigned)lane; cur_idx = c_i; }
          thr = mp;   // lazy lower bound (pre-insertion min)
        }
      }
    }
  }
  g_knn[(size_t)row*KK + lane] = cur_idx;
}

// -------------------- 4. factorized attention + fused BN1 stats ------------------
#define AT_WARPS 16
#define AT_WBUF 2688
#define DIFF_LD 68

__global__ __launch_bounds__(512) void attn_kernel(const float* __restrict__ wq,
                                                   const float* __restrict__ wk,
                                                   const float* __restrict__ wv){
  extern __shared__ float smf[];
  float2* wq2 = (float2*)smf;
  float2* wv2 = wq2 + 2048;
  float2* wk2 = wv2 + 2048;
  int tid = threadIdx.x;
  int lane = tid & 31, wid = tid >> 5;
  float* wb    = smf + 12288 + wid*AT_WBUF;
  float* sdiff = wb;
  float* sfn   = wb + 2176;
  float* sq    = wb + 2240;
  float* sqk   = wb + 2304;
  float* sattn = wb + 2560;
  float* swd   = sqk;

  for (int idx = tid; idx < 2048; idx += 512){
    int cc = idx >> 5, oo = idx & 31;
    wq2[idx] = make_float2(wq[oo*64 + cc], wq[(oo+32)*64 + cc]);
    wv2[idx] = make_float2(wv[oo*64 + cc], wv[(oo+32)*64 + cc]);
    int o = idx >> 5, c = idx & 31;
    wk2[idx] = make_float2(wk[o*64 + c], wk[o*64 + c + 32]);
  }
  __syncthreads();

  int rowbase = blockIdx.x * (AT_WARPS*4);
  float s0 = 0.f, q0s = 0.f, s1 = 0.f, q1s = 0.f;   // BN1 partials

  for (int rr = 0; rr < 4; rr++){
    int row = rowbase + wid*4 + rr;
    int b = row >> 12;

    sfn[lane]      = g_feat[(size_t)row*CC + lane];
    sfn[lane + 32] = g_feat[(size_t)row*CC + lane + 32];
    __syncwarp();

    // coalesced gather: 4 lanes per neighbor row (8 rows per pass, 4 passes)
    {
      int nbr0 = g_knn[(size_t)row*KK + lane];
      int seg = lane & 3;
      const float* fbb = g_feat + ((size_t)(b<<12))*CC;
#pragma unroll
      for (int p = 0; p < 4; p++){
        int nk  = (lane >> 2) + 8*p;
        int nbr = __shfl_sync(FULLMASK, nbr0, nk);
        const float4* src = (const float4*)(fbb + (size_t)nbr*CC);
        float4* drow = (float4*)(sdiff + nk*DIFF_LD);
#pragma unroll
        for (int j = 0; j < 4; j++){
          int c4 = seg + 4*j;
          float4 v = src[c4];
          float4 f = *(const float4*)(sfn + c4*4);
          drow[c4] = make_float4(v.x-f.x, v.y-f.y, v.z-f.z, v.w-f.w);
        }
      }
    }

    {
      float q0 = 0.f, q1 = 0.f;
#pragma unroll
      for (int c4 = 0; c4 < 16; c4++){
        float4 f = *(const float4*)(sfn + c4*4);
        float2 w0 = wq2[(c4*4  )*32 + lane];
        float2 w1 = wq2[(c4*4+1)*32 + lane];
        float2 w2 = wq2[(c4*4+2)*32 + lane];
        float2 w3 = wq2[(c4*4+3)*32 + lane];
        q0 += f.x*w0.x + f.y*w1.x + f.z*w2.x + f.w*w3.x;
        q1 += f.x*w0.y + f.y*w1.y + f.z*w2.y + f.w*w3.y;
      }
      sq[lane] = q0; sq[lane+32] = q1;
    }
    __syncwarp();

    {
      float a[8];
#pragma unroll
      for (int t=0;t<8;t++) a[t]=0.f;
#pragma unroll
      for (int o = 0; o < 64; o++){
        int h = o >> 4;
        float qb = sq[o];
        float2 w = wk2[o*32 + lane];
        a[h*2  ] += qb*w.x;
        a[h*2+1] += qb*w.y;
      }
#pragma unroll
      for (int h=0;h<4;h++){
        sqk[h*64 + lane]      = a[h*2];
        sqk[h*64 + lane + 32] = a[h*2+1];
      }
    }
    __syncwarp();

    {
      float e0=0.f,e1=0.f,e2=0.f,e3=0.f;
      const float4* drow = (const float4*)(sdiff + lane*DIFF_LD);
#pragma unroll
      for (int c4 = 0; c4 < 16; c4++){
        float4 d = drow[c4];
        float4 k0 = *(const float4*)(sqk + 0*64 + c4*4);
        float4 k1 = *(const float4*)(sqk + 1*64 + c4*4);
        float4 k2 = *(const float4*)(sqk + 2*64 + c4*4);
        float4 k3 = *(const float4*)(sqk + 3*64 + c4*4);
        e0 += d.x*k0.x + d.y*k0.y + d.z*k0.z + d.w*k0.w;
        e1 += d.x*k1.x + d.y*k1.y + d.z*k1.z + d.w*k1.w;
        e2 += d.x*k2.x + d.y*k2.y + d.z*k2.z + d.w*k2.w;
        e3 += d.x*k3.x + d.y*k3.y + d.z*k3.z + d.w*k3.w;
      }
      float e[4] = {e0*0.25f, e1*0.25f, e2*0.25f, e3*0.25f};
      float a[4];
#pragma unroll
      for (int h=0;h<4;h++){
        float mx = warp_max32(e[h]);
        float ex = __expf(e[h]-mx);
        float s  = warp_sum32(ex);
        a[h] = ex / s;
      }
      *(float4*)(sattn + lane*4) = make_float4(a[0],a[1],a[2],a[3]);
    }
    __syncwarp();

    {
      float w[8];
#pragma unroll
      for (int t=0;t<8;t++) w[t]=0.f;
#pragma unroll
      for (int k = 0; k < 32; k++){
        float4 at = *(const float4*)(sattn + k*4);
        float d0 = sdiff[k*DIFF_LD + lane];
        float d1 = sdiff[k*DIFF_LD + lane + 32];
        w[0]+=at.x*d0; w[1]+=at.x*d1;
        w[2]+=at.y*d0; w[3]+=at.y*d1;
        w[4]+=at.z*d0; w[5]+=at.z*d1;
        w[6]+=at.w*d0; w[7]+=at.w*d1;
      }
      __syncwarp();
#pragma unroll
      for (int h=0;h<4;h++){
        swd[h*64 + lane]      = w[h*2];
        swd[h*64 + lane + 32] = w[h*2+1];
      }
    }
    __syncwarp();

    {
      int h0 = lane >> 4;
      float o0 = 0.f, o1 = 0.f;
#pragma unroll
      for (int c4 = 0; c4 < 16; c4++){
        float4 d0 = *(const float4*)(swd + h0*64     + c4*4);
        float4 d1 = *(const float4*)(swd + (h0+2)*64 + c4*4);
        float2 w0 = wv2[(c4*4  )*32 + lane];
        float2 w1 = wv2[(c4*4+1)*32 + lane];
        float2 w2 = wv2[(c4*4+2)*32 + lane];
        float2 w3 = wv2[(c4*4+3)*32 + lane];
        o0 += d0.x*w0.x + d0.y*w1.x + d0.z*w2.x + d0.w*w3.x;
        o1 += d1.x*w0.y + d1.y*w1.y + d1.z*w2.y + d1.w*w3.y;
      }
      float f00 = sfn[lane]      + o0;
      float f01 = sfn[lane + 32] + o1;
      g_f0[(size_t)row*CC + lane]      = f00;
      g_f0[(size_t)row*CC + lane + 32] = f01;
      s0 += f00; q0s += f00*f00;
      s1 += f01; q1s += f01*f01;
    }
    __syncwarp();
  }

  // fused BN1 stats
  __syncthreads();
  float2* sc0 = (float2*)smf;
  float2* sc1 = sc0 + 512;
  sc0[wid*32 + lane] = make_float2(s0, q0s);
  sc1[wid*32 + lane] = make_float2(s1, q1s);
  __syncthreads();
  if (tid < 64){
    const float2* srcp = (tid < 32) ? (sc0 + tid) : (sc1 + (tid - 32));
    float s = 0.f, q = 0.f;
#pragma unroll
    for (int w = 0; w < 16; w++){ float2 v = srcp[w*32]; s += v.x; q += v.y; }
    g_psum[blockIdx.x*64 + tid] = s;
    g_psq [blockIdx.x*64 + tid] = q;
  }
}

// -------------------- 5. BN finalize (512 partials) --------------------
__global__ void bn_finalize_kernel(){
  __shared__ float ps[256], pq[256];
  int c = threadIdx.x & 63, part = threadIdx.x >> 6;
  float s = 0.f, q = 0.f;
  for (int i = part; i < 512; i += 4){ s += g_psum[i*64 + c]; q += g_psq[i*64 + c]; }
  ps[threadIdx.x] = s; pq[threadIdx.x] = q;
  __syncthreads();
  if (threadIdx.x < 64){
    s = ps[c] + ps[c+64] + ps[c+128] + ps[c+192];
    q = pq[c] + pq[c+64] + pq[c+128] + pq[c+192];
    float m   = s * (1.f/32768.f);
    float var = q * (1.f/32768.f) - m*m;
    g_mu[c] = m;
    g_rs[c] = rsqrtf(var + 1e-5f);
  }
}

// -------------------- 6a. MLP layer 1: BN1-normalize + w1 + LeakyReLU ----------
#define MLP1_SMEM ((16384 + 256)*4)
__global__ __launch_bounds__(256,3) void mlp1_kernel(const float* __restrict__ w1,
                                                     const float* __restrict__ g1,
                                                     const float* __restrict__ b1){
  extern __shared__ float smf[];
  float* w1T  = smf;              // [c][o] 64x256
  float* sf1T = smf + 16384;      // [c][j] 64x4
  __shared__ float ssc[64], ssh[64];
  int tid = threadIdx.x;

  {
    int o = tid;
#pragma unroll
    for (int c4 = 0; c4 < 16; c4++){
      float4 v = *(const float4*)(w1 + o*64 + c4*4);
      int c = c4*4;
      w1T[c*256+o]=v.x; w1T[(c+1)*256+o]=v.y; w1T[(c+2)*256+o]=v.z; w1T[(c+3)*256+o]=v.w;
    }
  }
  if (tid < 64){
    float r = g_rs[tid] * g1[tid];
    ssc[tid] = r;
    ssh[tid] = b1[tid] - g_mu[tid]*r;
  }
  __syncthreads();

  int rowbase = blockIdx.x * 64;
  for (int it = 0; it < 16; it++){
    int row0 = rowbase + it*4;
    {
      int c = tid >> 2, j = tid & 3;
      sf1T[tid] = g_f0[(size_t)(row0+j)*CC + c]*ssc[c] + ssh[c];
    }
    __syncthreads();
    float h0=0.f,h1=0.f,h2=0.f,h3=0.f;
#pragma unroll
    for (int c = 0; c < 64; c++){
      float w = w1T[c*256 + tid];
      float4 f = *(const float4*)(sf1T + c*4);
      h0+=f.x*w; h1+=f.y*w; h2+=f.z*w; h3+=f.w*w;
    }
    h0 = (h0>0.f)?h0:0.2f*h0; h1 = (h1>0.f)?h1:0.2f*h1;
    h2 = (h2>0.f)?h2:0.2f*h2; h3 = (h3>0.f)?h3:0.2f*h3;
    g_hid[(size_t)(row0+0)*256 + tid] = h0;
    g_hid[(size_t)(row0+1)*256 + tid] = h1;
    g_hid[(size_t)(row0+2)*256 + tid] = h2;
    g_hid[(size_t)(row0+3)*256 + tid] = h3;
    __syncthreads();
  }
}

// -------------------- 6b. MLP layer 2: w2 + residual + fused BN2 stats ----------
#define MLP2_SMEM ((16384 + 1024 + 256 + 1024)*4)
__global__ __launch_bounds__(256,3) void mlp2_kernel(const float* __restrict__ w2,
                                                     const float* __restrict__ g1,
                                                     const float* __restrict__ b1){
  extern __shared__ float smf[];
  float* w2T   = smf;              // [o][c] 256x64
  float* shT   = smf + 16384;      // [o][j] 256x4
  float* sf1T  = smf + 17408;      // [c][j] 64x4
  float* spart = smf + 17664;      // 1024
  __shared__ float ssc[64], ssh[64];
  int tid = threadIdx.x;

  {
    int c = tid & 63, o4b = tid >> 6;
#pragma unroll
    for (int it = 0; it < 16; it++){
      int o2 = (o4b + 4*it) * 4;
      float4 v = *(const float4*)(w2 + c*256 + o2);
      w2T[o2*64+c]=v.x; w2T[(o2+1)*64+c]=v.y; w2T[(o2+2)*64+c]=v.z; w2T[(o2+3)*64+c]=v.w;
    }
  }
  if (tid < 64){
    float r = g_rs[tid] * g1[tid];
    ssc[tid] = r;
    ssh[tid] = b1[tid] - g_mu[tid]*r;
  }
  __syncthreads();

  int rowbase = blockIdx.x * 64;
  float s_loc = 0.f, q_loc = 0.f;
  for (int it = 0; it < 16; it++){
    int row0 = rowbase + it*4;
    {
      int c = tid >> 2, j = tid & 3;
      sf1T[tid] = g_f0[(size_t)(row0+j)*CC + c]*ssc[c] + ssh[c];
    }
#pragma unroll
    for (int j = 0; j < 4; j++)
      shT[tid*4 + j] = g_hid[(size_t)(row0+j)*256 + tid];
    __syncthreads();
    {
      int c = tid & 63, part = tid >> 6;
      float p0=0.f,p1=0.f,p2=0.f,p3=0.f;
#pragma unroll
      for (int oo = 0; oo < 64; oo++){
        int o = part*64 + oo;
        float w = w2T[o*64 + c];
        float4 hv = *(const float4*)(shT + o*4);
        p0+=hv.x*w; p1+=hv.y*w; p2+=hv.z*w; p3+=hv.w*w;
      }
      spart[(0*4+part)*64 + c] = p0;
      spart[(1*4+part)*64 + c] = p1;
      spart[(2*4+part)*64 + c] = p2;
      spart[(3*4+part)*64 + c] = p3;
    }
    __syncthreads();
    {
      int c = tid & 63, j = tid >> 6;
      float ff = spart[(j*4+0)*64+c] + spart[(j*4+1)*64+c]
               + spart[(j*4+2)*64+c] + spart[(j*4+3)*64+c];
      float v = sf1T[c*4+j] + ff;
      g_f2[(size_t)(row0+j)*CC + c] = v;
      s_loc += v; q_loc += v*v;
    }
    __syncthreads();
  }

  {
    int c = tid & 63, j = tid >> 6;
    spart[j*64 + c]       = s_loc;
    spart[(4+j)*64 + c]   = q_loc;
  }
  __syncthreads();
  if (tid < 64){
    float s = spart[tid] + spart[64+tid] + spart[128+tid] + spart[192+tid];
    float q = spart[256+tid] + spart[320+tid] + spart[384+tid] + spart[448+tid];
    g_psum[blockIdx.x*64 + tid] = s;
    g_psq [blockIdx.x*64 + tid] = q;
  }
}

// -------------------- 7. BN2-normalize + transpose to (B,C,N) --------------------
__global__ void out_kernel(const float* __restrict__ g2, const float* __restrict__ b2,
                           float* __restrict__ out){
  __shared__ float tile[32][33];
  int b  = blockIdx.z;
  int c0 = blockIdx.y * 32;
  int n0 = blockIdx.x * 32;
  int tx = threadIdx.x, ty = threadIdx.y;
  const float* fb = g_f2 + (size_t)b*NN*CC;
#pragma unroll
  for (int i = 0; i < 32; i += 8)
    tile[ty+i][tx] = fb[(size_t)(n0+ty+i)*CC + c0 + tx];
  __syncthreads();
#pragma unroll
  for (int i = 0; i < 32; i += 8){
    int c = c0 + ty + i;
    float sc = g_rs[c]*g2[c];
    float sh = b2[c] - g_mu[c]*sc;
    out[((size_t)b*CC + c)*NN + n0 + tx] = tile[tx][ty+i]*sc + sh;
  }
}

// -------------------- launch --------------------
extern "C" void kernel_launch(void* const* d_in, const int* in_sizes, int n_in,
                              void* d_out, int out_size){
  (void)in_sizes; (void)n_in; (void)out_size;
  const float* x  = (const float*)d_in[0];
  const float* wq = (const float*)d_in[1];
  const float* wk = (const float*)d_in[2];
  const float* wv = (const float*)d_in[3];
  const float* w1 = (const float*)d_in[4];
  const float* w2 = (const float*)d_in[5];
  const float* g1 = (const float*)d_in[6];
  const float* b1 = (const float*)d_in[7];
  const float* g2 = (const float*)d_in[8];
  const float* b2 = (const float*)d_in[9];
  float* out = (float*)d_out;

  const int ATTN_SMEM = (12288 + AT_WARPS*AT_WBUF) * 4;
  cudaFuncSetAttribute(gram_kernel, cudaFuncAttributeMaxDynamicSharedMemorySize, KNN_SMEM_BYTES);
  cudaFuncSetAttribute(attn_kernel, cudaFuncAttributeMaxDynamicSharedMemorySize, ATTN_SMEM);
  cudaFuncSetAttribute(mlp1_kernel, cudaFuncAttributeMaxDynamicSharedMemorySize, MLP1_SMEM);
  cudaFuncSetAttribute(mlp2_kernel, cudaFuncAttributeMaxDynamicSharedMemorySize, MLP2_SMEM);

  transpose_kernel<<<dim3(NN/32, CC/32, BB), dim3(32,8)>>>(x);
  sqnorm_kernel<<<ROWS/256, 256>>>();
  gram_kernel<<<dim3(NN/64, BB), 256, KNN_SMEM_BYTES>>>(x);
  topk_kernel<<<ROWS/8, 256>>>();
  attn_kernel<<<ROWS/(AT_WARPS*4), 512, ATTN_SMEM>>>(wq, wk, wv);
  bn_finalize_kernel<<<1, 256>>>();
  mlp1_kernel<<<ROWS/64, 256, MLP1_SMEM>>>(w1, g1, b1);
  mlp2_kernel<<<ROWS/64, 256, MLP2_SMEM>>>(w2, g1, b1);
  bn_finalize_kernel<<<1, 256>>>();
  out_kernel<<<dim3(NN/32, CC/32, BB), dim3(32,8)>>>(g2, b2, out);
}